// round 3
// baseline (speedup 1.0000x reference)
#include <cuda_runtime.h>
#include <math.h>

#define T_LEN 16384
#define NB 4

static __device__ __forceinline__ float sigmoidf_(float v) {
    return 1.0f / (1.0f + __expf(-v));
}

#define SQRT_HALF_F 0.70710678118654752f

typedef unsigned long long ull;

// packed f32x2 helpers (sm_103a FFMA2 path — ptxas never auto-emits)
static __device__ __forceinline__ ull pack2(float v) {
    ull r;
    asm("mov.b64 %0, {%1, %1};" : "=l"(r) : "f"(v));
    return r;
}
static __device__ __forceinline__ void fma2(ull& d, ull a, ull b) {
    asm("fma.rn.f32x2 %0, %1, %2, %0;" : "+l"(d) : "l"(a), "l"(b));
}
static __device__ __forceinline__ float2 unpack2(ull v) {
    float2 r;
    asm("mov.b64 {%0, %1}, %2;" : "=f"(r.x), "=f"(r.y) : "l"(v));
    return r;
}

// ---------------- scratch (allocation-free: __device__ globals) ----------------
__device__ float g_h[2][NB * 64 * T_LEN];     // residual ping-pong
__device__ float g_z[NB * 64 * T_LEN];        // gated activations per layer
__device__ float g_skip[NB * 256 * T_LEN];    // skip accumulator
__device__ float g_tmp[NB * 256 * T_LEN];     // final intermediate

// =======================================================================
// Kernel 1: first conv (k=2 causal, 256 -> 64) + tanh. (unchanged)
// =======================================================================
#define FIRST_SMEM 200960
__global__ __launch_bounds__(256) void first_kernel(
    const float* __restrict__ x, const float* __restrict__ Wf,
    const float* __restrict__ bf)
{
    extern __shared__ float sm[];
    float* Wf_s = sm;              // ic*128 + k*64 + oc
    float* bs   = Wf_s + 32768;    // 64
    float* Xs   = bs + 64;         // ic*68 + jj

    int tid = threadIdx.x;
    for (int i = tid; i < 64 * 256 * 2; i += 256) {
        int oc = i >> 9; int ic = (i >> 1) & 255; int k = i & 1;
        Wf_s[ic * 128 + k * 64 + oc] = Wf[i];
    }
    if (tid < 64) bs[tid] = bf[tid];
    __syncthreads();

    int tq = tid & 7, grp = tid >> 3;
    int tb = tq * 8, oc2 = grp * 2;

    for (int tile = blockIdx.x; tile < NB * 256; tile += gridDim.x) {
        int b = tile >> 8;
        int t0 = (tile & 255) << 6;
        __syncthreads();
        for (int i = tid; i < 256 * 65; i += 256) {
            int ic = i / 65, jj = i - ic * 65;
            int t = (jj < 64) ? (t0 + jj) : (t0 - 1);
            Xs[ic * 68 + jj] = (t >= 0) ? x[((b * 256 + ic) << 14) + t] : 0.f;
        }
        __syncthreads();

        float acc[2][8];
#pragma unroll
        for (int a = 0; a < 2; a++)
#pragma unroll
            for (int j = 0; j < 8; j++) acc[a][j] = 0.f;

#pragma unroll 2
        for (int ic = 0; ic < 256; ic++) {
            const float* xp = Xs + ic * 68 + tb;
            float4 x0 = *(const float4*)xp;
            float4 x1 = *(const float4*)(xp + 4);
            float xm1 = (tb == 0) ? Xs[ic * 68 + 64] : Xs[ic * 68 + tb - 1];
            float2 w0 = *(const float2*)(Wf_s + ic * 128 + oc2);
            float2 w1 = *(const float2*)(Wf_s + ic * 128 + 64 + oc2);
            float xc[8] = {x0.x, x0.y, x0.z, x0.w, x1.x, x1.y, x1.z, x1.w};
            float xpv[8] = {xm1, xc[0], xc[1], xc[2], xc[3], xc[4], xc[5], xc[6]};
            float wa[2] = {w0.x, w0.y};
            float wb[2] = {w1.x, w1.y};
#pragma unroll
            for (int a = 0; a < 2; a++)
#pragma unroll
                for (int j = 0; j < 8; j++)
                    acc[a][j] += wa[a] * xpv[j] + wb[a] * xc[j];
        }

#pragma unroll
        for (int a = 0; a < 2; a++) {
            int oc = oc2 + a;
            float bv = bs[oc];
            float* hp = &g_h[0][((b * 64 + oc) << 14) + t0 + tb];
            float4 v0, v1;
            v0.x = tanhf(acc[a][0] + bv); v0.y = tanhf(acc[a][1] + bv);
            v0.z = tanhf(acc[a][2] + bv); v0.w = tanhf(acc[a][3] + bv);
            v1.x = tanhf(acc[a][4] + bv); v1.y = tanhf(acc[a][5] + bv);
            v1.z = tanhf(acc[a][6] + bv); v1.w = tanhf(acc[a][7] + bv);
            *(float4*)hp = v0;
            *(float4*)(hp + 4) = v1;
        }
    }
}

// =======================================================================
// Kernel 2 (v3): gate. Tile = 128 gates x 128 t. 512 threads.
// Warp computes 32g x 32t (thread: 4g x 8t). Taps in 3 passes over one
// Hs buffer. Gates permuted pg = 2*(g%64) + g/64 so each thread holds the
// (tanh, sigmoid) pair -> z computed in registers, no smem roundtrip.
// SMEM floats: Wd 24576 | Wc 10240 | bias 128 | Hs 8192 | Cs 10240 = 53376
// =======================================================================
#define GATE_SMEM (53376 * 4)
__global__ __launch_bounds__(512) void gate_kernel(
    int layer, int dil, int hsel,
    const float* __restrict__ c,
    const float* __restrict__ W_dil, const float* __restrict__ b_dil,
    const float* __restrict__ W_c, const float* __restrict__ b_c)
{
    extern __shared__ float sm[];
    float* Wd_s = sm;               // r*384 + k*128 + pg
    float* Wc_s = sm + 24576;       // ci*128 + pg
    float* bs   = sm + 34816;       // pg
    float* Hs   = sm + 34944;       // r*128 + j
    float* Cs   = sm + 43136;       // ci*128 + j

    int tid = threadIdx.x;
    const float* Wd = W_dil + layer * 24576;
    const float* Wc = W_c + layer * 10240;
    const float* h_in = g_h[hsel];

    for (int i = tid; i < 24576; i += 512) {
        int g = i / 192; int rem = i - g * 192; int r = rem / 3; int k = rem - r * 3;
        int pg = ((g & 63) << 1) | (g >> 6);
        Wd_s[r * 384 + k * 128 + pg] = Wd[i];
    }
    for (int i = tid; i < 10240; i += 512) {
        int g = i / 80; int ci = i - g * 80;
        int pg = ((g & 63) << 1) | (g >> 6);
        Wc_s[ci * 128 + pg] = Wc[i];
    }
    if (tid < 128) {
        int g = ((tid & 1) ? 64 : 0) + (tid >> 1);
        bs[tid] = b_dil[layer * 128 + g] + b_c[layer * 128 + g];
    }
    __syncthreads();

    int lane = tid & 31, warp = tid >> 5;
    int wg = warp & 3, wt = warp >> 2;
    int gg = lane >> 2, tg = lane & 3;
    int G4 = (wg * 8 + gg) * 4;      // permuted gate base
    int TB = (wt * 4 + tg) * 8;      // time base within tile

    for (int tile = blockIdx.x; tile < NB * 128; tile += gridDim.x) {
        int b = tile >> 7;
        int t0 = (tile & 127) << 7;

        ull acc[4][4];
#pragma unroll
        for (int a = 0; a < 4; a++)
#pragma unroll
            for (int p = 0; p < 4; p++) acc[a][p] = 0ull;

        __syncthreads();   // previous tile's Hs/Cs reads complete
        for (int i = tid; i < 10240; i += 512) {
            int ci = i >> 7, j = i & 127;
            Cs[i] = c[((b * 80 + ci) << 14) + t0 + j];
        }

#pragma unroll 1
        for (int k = 0; k < 3; k++) {
            if (k) __syncthreads();            // previous tap's reads done
            int shift = (2 - k) * dil;
            for (int i = tid; i < 8192; i += 512) {
                int r = i >> 7, j = i & 127;
                int t = t0 + j - shift;
                Hs[i] = (t >= 0) ? h_in[((b * 64 + r) << 14) + t] : 0.f;
            }
            __syncthreads();

            const float* wbase = Wd_s + k * 128 + G4;
#pragma unroll 4
            for (int r = 0; r < 64; r++) {
                float4 w = *(const float4*)(wbase + r * 384);
                ulonglong2 hA = *(const ulonglong2*)(Hs + r * 128 + TB);
                ulonglong2 hB = *(const ulonglong2*)(Hs + r * 128 + TB + 4);
                ull w0 = pack2(w.x), w1 = pack2(w.y), w2 = pack2(w.z), w3 = pack2(w.w);
                ull hv0 = hA.x, hv1 = hA.y, hv2 = hB.x, hv3 = hB.y;
                fma2(acc[0][0], w0, hv0); fma2(acc[1][0], w1, hv0);
                fma2(acc[2][0], w2, hv0); fma2(acc[3][0], w3, hv0);
                fma2(acc[0][1], w0, hv1); fma2(acc[1][1], w1, hv1);
                fma2(acc[2][1], w2, hv1); fma2(acc[3][1], w3, hv1);
                fma2(acc[0][2], w0, hv2); fma2(acc[1][2], w1, hv2);
                fma2(acc[2][2], w2, hv2); fma2(acc[3][2], w3, hv2);
                fma2(acc[0][3], w0, hv3); fma2(acc[1][3], w1, hv3);
                fma2(acc[2][3], w2, hv3); fma2(acc[3][3], w3, hv3);
            }
        }

        // conditioning GEMM (Cs loaded at tile start, untouched since)
#pragma unroll 4
        for (int ci = 0; ci < 80; ci++) {
            float4 w = *(const float4*)(Wc_s + ci * 128 + G4);
            ulonglong2 cA = *(const ulonglong2*)(Cs + ci * 128 + TB);
            ulonglong2 cB = *(const ulonglong2*)(Cs + ci * 128 + TB + 4);
            ull w0 = pack2(w.x), w1 = pack2(w.y), w2 = pack2(w.z), w3 = pack2(w.w);
            ull cv0 = cA.x, cv1 = cA.y, cv2 = cB.x, cv3 = cB.y;
            fma2(acc[0][0], w0, cv0); fma2(acc[1][0], w1, cv0);
            fma2(acc[2][0], w2, cv0); fma2(acc[3][0], w3, cv0);
            fma2(acc[0][1], w0, cv1); fma2(acc[1][1], w1, cv1);
            fma2(acc[2][1], w2, cv1); fma2(acc[3][1], w3, cv1);
            fma2(acc[0][2], w0, cv2); fma2(acc[1][2], w1, cv2);
            fma2(acc[2][2], w2, cv2); fma2(acc[3][2], w3, cv2);
            fma2(acc[0][3], w0, cv3); fma2(acc[1][3], w1, cv3);
            fma2(acc[2][3], w2, cv3); fma2(acc[3][3], w3, cv3);
        }

        // epilogue: z = tanh(a) * sigmoid(bgate) in registers
        // pg G4+0 = a-half chan m0, +1 = b-half chan m0, +2/+3 = chan m0+1
        int m0 = G4 >> 1;
        float ba0 = bs[G4 + 0], bb0 = bs[G4 + 1];
        float ba1 = bs[G4 + 2], bb1 = bs[G4 + 3];
        float z0[8], z1[8];
#pragma unroll
        for (int p = 0; p < 4; p++) {
            float2 ya0 = unpack2(acc[0][p]);
            float2 yb0 = unpack2(acc[1][p]);
            float2 ya1 = unpack2(acc[2][p]);
            float2 yb1 = unpack2(acc[3][p]);
            z0[2 * p]     = tanhf(ya0.x + ba0) * sigmoidf_(yb0.x + bb0);
            z0[2 * p + 1] = tanhf(ya0.y + ba0) * sigmoidf_(yb0.y + bb0);
            z1[2 * p]     = tanhf(ya1.x + ba1) * sigmoidf_(yb1.x + bb1);
            z1[2 * p + 1] = tanhf(ya1.y + ba1) * sigmoidf_(yb1.y + bb1);
        }
        float* zp0 = &g_z[((b * 64 + m0) << 14) + t0 + TB];
        float* zp1 = zp0 + (1 << 14);
        *(float4*)zp0       = make_float4(z0[0], z0[1], z0[2], z0[3]);
        *(float4*)(zp0 + 4) = make_float4(z0[4], z0[5], z0[6], z0[7]);
        *(float4*)zp1       = make_float4(z1[0], z1[1], z1[2], z1[3]);
        *(float4*)(zp1 + 4) = make_float4(z1[4], z1[5], z1[6], z1[7]);
    }
}

// =======================================================================
// Kernel 3 (v3): skip + out. Same math as R2, but 2 CTAs/SM.
// =======================================================================
#define SKIPOUT_SMEM 99584
__global__ __launch_bounds__(512, 2) void skipout_kernel(
    int layer, int hsel,
    const float* __restrict__ W_skip, const float* __restrict__ b_skip,
    const float* __restrict__ W_out, const float* __restrict__ b_out)
{
    extern __shared__ float sm[];
    float* Wsk_s = sm;                  // r*256 + sc
    float* Wo_s  = Wsk_s + 16384;       // r*64 + oc
    float* bsk_s = Wo_s + 4096;         // 256
    float* bo_s  = bsk_s + 256;         // 64
    float* Zs    = bo_s + 64;           // r*64 + t

    int tid = threadIdx.x;
    const float* Wsk = W_skip + layer * 256 * 64;
    const float* Wo  = W_out + layer * 64 * 64;
    const float* h_in = g_h[hsel];
    float* h_out = g_h[1 - hsel];

    for (int i = tid; i < 256 * 64; i += 512) {
        int sc = i >> 6; int r = i & 63;
        Wsk_s[r * 256 + sc] = Wsk[i];
    }
    for (int i = tid; i < 64 * 64; i += 512) {
        int oc = i >> 6; int r = i & 63;
        Wo_s[r * 64 + oc] = Wo[i];
    }
    if (tid < 256) bsk_s[tid] = b_skip[layer * 256 + tid];
    if (tid < 64)  bo_s[tid]  = b_out[layer * 64 + tid];
    __syncthreads();

    int tq = tid & 7, grp = tid >> 3;   // grp 0..63
    int tb = tq * 8;
    int sc4 = grp * 4;
    int oc1 = grp;

    for (int tile = blockIdx.x; tile < NB * 256; tile += gridDim.x) {
        int b = tile >> 8;
        int t0 = (tile & 255) << 6;
        __syncthreads();
        for (int i = tid; i < 4096; i += 512) {
            int r = i >> 6; int j = i & 63;
            Zs[i] = g_z[((b * 64 + r) << 14) + t0 + j];
        }
        __syncthreads();

        ull accS[4][4];
        ull accO[4];
#pragma unroll
        for (int a = 0; a < 4; a++) {
            accO[a] = 0ull;
#pragma unroll
            for (int p = 0; p < 4; p++) accS[a][p] = 0ull;
        }

#pragma unroll 2
        for (int r = 0; r < 64; r++) {
            const float* zp = Zs + r * 64 + tb;
            ulonglong2 zA = *(const ulonglong2*)zp;
            ulonglong2 zB = *(const ulonglong2*)(zp + 4);
            float4 ws = *(const float4*)(Wsk_s + r * 256 + sc4);
            ull w0 = pack2(ws.x), w1 = pack2(ws.y), w2 = pack2(ws.z), w3 = pack2(ws.w);
            ull wo = pack2(Wo_s[r * 64 + oc1]);
            fma2(accS[0][0], w0, zA.x); fma2(accS[1][0], w1, zA.x);
            fma2(accS[2][0], w2, zA.x); fma2(accS[3][0], w3, zA.x);
            fma2(accO[0], wo, zA.x);
            fma2(accS[0][1], w0, zA.y); fma2(accS[1][1], w1, zA.y);
            fma2(accS[2][1], w2, zA.y); fma2(accS[3][1], w3, zA.y);
            fma2(accO[1], wo, zA.y);
            fma2(accS[0][2], w0, zB.x); fma2(accS[1][2], w1, zB.x);
            fma2(accS[2][2], w2, zB.x); fma2(accS[3][2], w3, zB.x);
            fma2(accO[2], wo, zB.x);
            fma2(accS[0][3], w0, zB.y); fma2(accS[1][3], w1, zB.y);
            fma2(accS[2][3], w2, zB.y); fma2(accS[3][3], w3, zB.y);
            fma2(accO[3], wo, zB.y);
        }

        // skip accumulate
#pragma unroll
        for (int a = 0; a < 4; a++) {
            int sc = sc4 + a;
            float bsv = bsk_s[sc];
            float2 q0 = unpack2(accS[a][0]);
            float2 q1 = unpack2(accS[a][1]);
            float2 q2 = unpack2(accS[a][2]);
            float2 q3 = unpack2(accS[a][3]);
            float* sp = &g_skip[((b * 256 + sc) << 14) + t0 + tb];
            if (layer == 0) {
                float4 v0 = make_float4(q0.x + bsv, q0.y + bsv, q1.x + bsv, q1.y + bsv);
                float4 v1 = make_float4(q2.x + bsv, q2.y + bsv, q3.x + bsv, q3.y + bsv);
                *(float4*)sp = v0;
                *(float4*)(sp + 4) = v1;
            } else {
                float4 o0 = *(const float4*)sp;
                float4 o1 = *(const float4*)(sp + 4);
                float4 v0, v1;
                v0.x = (o0.x + q0.x + bsv) * SQRT_HALF_F;
                v0.y = (o0.y + q0.y + bsv) * SQRT_HALF_F;
                v0.z = (o0.z + q1.x + bsv) * SQRT_HALF_F;
                v0.w = (o0.w + q1.y + bsv) * SQRT_HALF_F;
                v1.x = (o1.x + q2.x + bsv) * SQRT_HALF_F;
                v1.y = (o1.y + q2.y + bsv) * SQRT_HALF_F;
                v1.z = (o1.z + q3.x + bsv) * SQRT_HALF_F;
                v1.w = (o1.w + q3.y + bsv) * SQRT_HALF_F;
                *(float4*)sp = v0;
                *(float4*)(sp + 4) = v1;
            }
        }

        // residual update (1 out channel per thread)
        {
            float bov = bo_s[oc1];
            float2 q0 = unpack2(accO[0]);
            float2 q1 = unpack2(accO[1]);
            float2 q2 = unpack2(accO[2]);
            float2 q3 = unpack2(accO[3]);
            const float* hip = h_in + ((b * 64 + oc1) << 14) + t0 + tb;
            float* hop = h_out + ((b * 64 + oc1) << 14) + t0 + tb;
            float4 h0 = *(const float4*)hip;
            float4 h1 = *(const float4*)(hip + 4);
            float4 v0, v1;
            v0.x = (q0.x + bov + h0.x) * SQRT_HALF_F;
            v0.y = (q0.y + bov + h0.y) * SQRT_HALF_F;
            v0.z = (q1.x + bov + h0.z) * SQRT_HALF_F;
            v0.w = (q1.y + bov + h0.w) * SQRT_HALF_F;
            v1.x = (q2.x + bov + h1.x) * SQRT_HALF_F;
            v1.y = (q2.y + bov + h1.y) * SQRT_HALF_F;
            v1.z = (q3.x + bov + h1.z) * SQRT_HALF_F;
            v1.w = (q3.y + bov + h1.w) * SQRT_HALF_F;
            *(float4*)hop = v0;
            *(float4*)(hop + 4) = v1;
        }
    }
}

// =======================================================================
// Kernel 4 (v3): dense 256x256, W staged in 32-row chunks -> 2 CTAs/SM.
// SMEM floats: Ss 16384 | Wt 32*260=8320 | bias 256 = 24960 (99840 B)
// =======================================================================
#define DENSE_SMEM 99840
__global__ __launch_bounds__(512, 2) void dense256_kernel(
    int stage, float* __restrict__ final_out,
    const float* __restrict__ W, const float* __restrict__ bias)
{
    extern __shared__ float sm[];
    float* Ss = sm;             // sc*64 + t
    float* Wt = Ss + 16384;     // scc*260 + oc  (scc < 32)
    float* bb = Wt + 8320;      // 256

    const float* in = (stage == 0) ? g_skip : g_tmp;
    float* out = (stage == 0) ? g_tmp : final_out;

    int tid = threadIdx.x;
    if (tid < 256) bb[tid] = bias[tid];

    int tq = tid & 7, ocg = tid >> 3;
    int tb = tq * 8, oc4 = ocg * 4;

    for (int tile = blockIdx.x; tile < NB * 256; tile += gridDim.x) {
        int b = tile >> 8;
        int t0 = (tile & 255) << 6;

        __syncthreads();
        for (int i = tid; i < 16384; i += 512) {
            int sc = i >> 6, j = i & 63;
            float v = in[((b * 256 + sc) << 14) + t0 + j];
            if (stage == 0) v = fmaxf(v, 0.f);
            Ss[i] = v;
        }

        ull acc[4][4];
#pragma unroll
        for (int a = 0; a < 4; a++)
#pragma unroll
            for (int p = 0; p < 4; p++) acc[a][p] = 0ull;

        for (int c0 = 0; c0 < 256; c0 += 32) {
            __syncthreads();
            for (int i = tid; i < 32 * 256; i += 512) {
                int scc = i & 31, oc = i >> 5;
                Wt[scc * 260 + oc] = W[oc * 256 + c0 + scc];
            }
            __syncthreads();
#pragma unroll 4
            for (int scc = 0; scc < 32; scc++) {
                const float* sp = Ss + (c0 + scc) * 64 + tb;
                ulonglong2 zA = *(const ulonglong2*)sp;
                ulonglong2 zB = *(const ulonglong2*)(sp + 4);
                float4 w = *(const float4*)(Wt + scc * 260 + oc4);
                ull w0 = pack2(w.x), w1 = pack2(w.y), w2 = pack2(w.z), w3 = pack2(w.w);
                fma2(acc[0][0], w0, zA.x); fma2(acc[1][0], w1, zA.x);
                fma2(acc[2][0], w2, zA.x); fma2(acc[3][0], w3, zA.x);
                fma2(acc[0][1], w0, zA.y); fma2(acc[1][1], w1, zA.y);
                fma2(acc[2][1], w2, zA.y); fma2(acc[3][1], w3, zA.y);
                fma2(acc[0][2], w0, zB.x); fma2(acc[1][2], w1, zB.x);
                fma2(acc[2][2], w2, zB.x); fma2(acc[3][2], w3, zB.x);
                fma2(acc[0][3], w0, zB.y); fma2(acc[1][3], w1, zB.y);
                fma2(acc[2][3], w2, zB.y); fma2(acc[3][3], w3, zB.y);
            }
        }

#pragma unroll
        for (int a = 0; a < 4; a++) {
            int oc = oc4 + a;
            float bv = bb[oc];
            float2 q0 = unpack2(acc[a][0]);
            float2 q1 = unpack2(acc[a][1]);
            float2 q2 = unpack2(acc[a][2]);
            float2 q3 = unpack2(acc[a][3]);
            float* op = out + ((b * 256 + oc) << 14) + t0 + tb;
            float4 v0 = make_float4(q0.x + bv, q0.y + bv, q1.x + bv, q1.y + bv);
            float4 v1 = make_float4(q2.x + bv, q2.y + bv, q3.x + bv, q3.y + bv);
            if (stage == 0) {
                v0.x = fmaxf(v0.x, 0.f); v0.y = fmaxf(v0.y, 0.f);
                v0.z = fmaxf(v0.z, 0.f); v0.w = fmaxf(v0.w, 0.f);
                v1.x = fmaxf(v1.x, 0.f); v1.y = fmaxf(v1.y, 0.f);
                v1.z = fmaxf(v1.z, 0.f); v1.w = fmaxf(v1.w, 0.f);
            }
            *(float4*)op = v0;
            *(float4*)(op + 4) = v1;
        }
    }
}

// =======================================================================
extern "C" void kernel_launch(void* const* d_in, const int* in_sizes, int n_in,
                              void* d_out, int out_size)
{
    const float* x       = (const float*)d_in[0];
    const float* c       = (const float*)d_in[1];
    const float* W_first = (const float*)d_in[2];
    const float* b_first = (const float*)d_in[3];
    const float* W_dil   = (const float*)d_in[4];
    const float* b_dil   = (const float*)d_in[5];
    const float* W_c     = (const float*)d_in[6];
    const float* b_c     = (const float*)d_in[7];
    const float* W_skip  = (const float*)d_in[8];
    const float* b_skip  = (const float*)d_in[9];
    const float* W_out   = (const float*)d_in[10];
    const float* b_out   = (const float*)d_in[11];
    const float* W_last1 = (const float*)d_in[12];
    const float* b_last1 = (const float*)d_in[13];
    const float* W_last2 = (const float*)d_in[14];
    const float* b_last2 = (const float*)d_in[15];
    float* out = (float*)d_out;

    cudaFuncSetAttribute(first_kernel,  cudaFuncAttributeMaxDynamicSharedMemorySize, FIRST_SMEM);
    cudaFuncSetAttribute(gate_kernel,   cudaFuncAttributeMaxDynamicSharedMemorySize, GATE_SMEM);
    cudaFuncSetAttribute(skipout_kernel,cudaFuncAttributeMaxDynamicSharedMemorySize, SKIPOUT_SMEM);
    cudaFuncSetAttribute(dense256_kernel,cudaFuncAttributeMaxDynamicSharedMemorySize, DENSE_SMEM);

    int dev = 0;
    cudaGetDevice(&dev);
    int sm_count = 148;
    cudaDeviceGetAttribute(&sm_count, cudaDevAttrMultiProcessorCount, dev);
    int grid1 = sm_count;
    int grid2 = 2 * sm_count;

    first_kernel<<<grid1, 256, FIRST_SMEM>>>(x, W_first, b_first);

    for (int l = 0; l < 20; l++) {
        int dil = 1 << (l % 10);
        int hsel = l & 1;   // layer l reads g_h[hsel], writes g_h[1-hsel]
        gate_kernel<<<grid1, 512, GATE_SMEM>>>(l, dil, hsel, c,
                                               W_dil, b_dil, W_c, b_c);
        skipout_kernel<<<grid2, 512, SKIPOUT_SMEM>>>(l, hsel,
                                                     W_skip, b_skip, W_out, b_out);
    }

    dense256_kernel<<<grid2, 512, DENSE_SMEM>>>(0, out, W_last1, b_last1);
    dense256_kernel<<<grid2, 512, DENSE_SMEM>>>(1, out, W_last2, b_last2);
}

// round 4
// speedup vs baseline: 1.0522x; 1.0522x over previous
#include <cuda_runtime.h>
#include <math.h>

#define T_LEN 16384
#define NB 4

static __device__ __forceinline__ float sigmoidf_(float v) {
    return 1.0f / (1.0f + __expf(-v));
}

#define SQRT_HALF_F 0.70710678118654752f

typedef unsigned long long ull;

// packed f32x2 helpers (sm_103a FFMA2 path — ptxas never auto-emits)
static __device__ __forceinline__ ull pack2(float v) {
    ull r;
    asm("mov.b64 %0, {%1, %1};" : "=l"(r) : "f"(v));
    return r;
}
static __device__ __forceinline__ void fma2(ull& d, ull a, ull b) {
    asm("fma.rn.f32x2 %0, %1, %2, %0;" : "+l"(d) : "l"(a), "l"(b));
}
static __device__ __forceinline__ float2 unpack2(ull v) {
    float2 r;
    asm("mov.b64 {%0, %1}, %2;" : "=f"(r.x), "=f"(r.y) : "l"(v));
    return r;
}

// ---------------- scratch (allocation-free: __device__ globals) ----------------
__device__ float g_h[2][NB * 64 * T_LEN];     // residual ping-pong
__device__ float g_z[NB * 64 * T_LEN];        // gated activations per layer
__device__ float g_skip[NB * 256 * T_LEN];    // skip accumulator
__device__ float g_tmp[NB * 256 * T_LEN];     // final intermediate

// =======================================================================
// Kernel 1: first conv (k=2 causal, 256 -> 64) + tanh. (unchanged)
// =======================================================================
#define FIRST_SMEM 200960
__global__ __launch_bounds__(256) void first_kernel(
    const float* __restrict__ x, const float* __restrict__ Wf,
    const float* __restrict__ bf)
{
    extern __shared__ float sm[];
    float* Wf_s = sm;              // ic*128 + k*64 + oc
    float* bs   = Wf_s + 32768;    // 64
    float* Xs   = bs + 64;         // ic*68 + jj

    int tid = threadIdx.x;
    for (int i = tid; i < 64 * 256 * 2; i += 256) {
        int oc = i >> 9; int ic = (i >> 1) & 255; int k = i & 1;
        Wf_s[ic * 128 + k * 64 + oc] = Wf[i];
    }
    if (tid < 64) bs[tid] = bf[tid];
    __syncthreads();

    int tq = tid & 7, grp = tid >> 3;
    int tb = tq * 8, oc2 = grp * 2;

    for (int tile = blockIdx.x; tile < NB * 256; tile += gridDim.x) {
        int b = tile >> 8;
        int t0 = (tile & 255) << 6;
        __syncthreads();
        for (int i = tid; i < 256 * 65; i += 256) {
            int ic = i / 65, jj = i - ic * 65;
            int t = (jj < 64) ? (t0 + jj) : (t0 - 1);
            Xs[ic * 68 + jj] = (t >= 0) ? x[((b * 256 + ic) << 14) + t] : 0.f;
        }
        __syncthreads();

        float acc[2][8];
#pragma unroll
        for (int a = 0; a < 2; a++)
#pragma unroll
            for (int j = 0; j < 8; j++) acc[a][j] = 0.f;

#pragma unroll 2
        for (int ic = 0; ic < 256; ic++) {
            const float* xp = Xs + ic * 68 + tb;
            float4 x0 = *(const float4*)xp;
            float4 x1 = *(const float4*)(xp + 4);
            float xm1 = (tb == 0) ? Xs[ic * 68 + 64] : Xs[ic * 68 + tb - 1];
            float2 w0 = *(const float2*)(Wf_s + ic * 128 + oc2);
            float2 w1 = *(const float2*)(Wf_s + ic * 128 + 64 + oc2);
            float xc[8] = {x0.x, x0.y, x0.z, x0.w, x1.x, x1.y, x1.z, x1.w};
            float xpv[8] = {xm1, xc[0], xc[1], xc[2], xc[3], xc[4], xc[5], xc[6]};
            float wa[2] = {w0.x, w0.y};
            float wb[2] = {w1.x, w1.y};
#pragma unroll
            for (int a = 0; a < 2; a++)
#pragma unroll
                for (int j = 0; j < 8; j++)
                    acc[a][j] += wa[a] * xpv[j] + wb[a] * xc[j];
        }

#pragma unroll
        for (int a = 0; a < 2; a++) {
            int oc = oc2 + a;
            float bv = bs[oc];
            float* hp = &g_h[0][((b * 64 + oc) << 14) + t0 + tb];
            float4 v0, v1;
            v0.x = tanhf(acc[a][0] + bv); v0.y = tanhf(acc[a][1] + bv);
            v0.z = tanhf(acc[a][2] + bv); v0.w = tanhf(acc[a][3] + bv);
            v1.x = tanhf(acc[a][4] + bv); v1.y = tanhf(acc[a][5] + bv);
            v1.z = tanhf(acc[a][6] + bv); v1.w = tanhf(acc[a][7] + bv);
            *(float4*)hp = v0;
            *(float4*)(hp + 4) = v1;
        }
    }
}

// =======================================================================
// Kernel 2 (v4): gate. Tile = 128 gates x 256 t. 512 threads.
// Thread = 8 permuted gates x 8 t (32 f32x2 accs).
// Warp = 64g x 32t. wg = warp&1 (gate half), wt = warp>>1 (t group).
// Union smem region: Cs (cond phase) then Hs (per-tap phases).
// SMEM floats: Wd 24576 | Wc 10240 | bias 128 | U 20480 = 55424 (221696 B)
// =======================================================================
#define GATE_SMEM (55424 * 4)
__global__ __launch_bounds__(512) void gate_kernel(
    int layer, int dil, int hsel,
    const float* __restrict__ c,
    const float* __restrict__ W_dil, const float* __restrict__ b_dil,
    const float* __restrict__ W_c, const float* __restrict__ b_c)
{
    extern __shared__ float sm[];
    float* Wd_s = sm;               // r*384 + k*128 + pg
    float* Wc_s = sm + 24576;       // ci*128 + pg
    float* bs   = sm + 34816;       // pg
    float* Us   = sm + 34944;       // Cs: ci*256+j (20480)  /  Hs: r*256+j (16384)

    int tid = threadIdx.x;
    const float* Wd = W_dil + layer * 24576;
    const float* Wc = W_c + layer * 10240;
    const float* h_in = g_h[hsel];

    for (int i = tid; i < 24576; i += 512) {
        int g = i / 192; int rem = i - g * 192; int r = rem / 3; int k = rem - r * 3;
        int pg = ((g & 63) << 1) | (g >> 6);
        Wd_s[r * 384 + k * 128 + pg] = Wd[i];
    }
    for (int i = tid; i < 10240; i += 512) {
        int g = i / 80; int ci = i - g * 80;
        int pg = ((g & 63) << 1) | (g >> 6);
        Wc_s[ci * 128 + pg] = Wc[i];
    }
    if (tid < 128) {
        int g = ((tid & 1) ? 64 : 0) + (tid >> 1);
        bs[tid] = b_dil[layer * 128 + g] + b_c[layer * 128 + g];
    }
    __syncthreads();

    int lane = tid & 31, warp = tid >> 5;
    int wg = warp & 1, wt = warp >> 1;
    int gg = lane >> 2, tg = lane & 3;
    int G8 = wg * 64 + gg * 8;       // permuted gate base (8 gates)
    int TB = wt * 32 + tg * 8;       // time base within tile (8 t)

    for (int tile = blockIdx.x; tile < NB * 64; tile += gridDim.x) {
        int b = tile >> 6;
        int t0 = (tile & 63) << 8;

        ull acc[8][4];
#pragma unroll
        for (int a = 0; a < 8; a++)
#pragma unroll
            for (int p = 0; p < 4; p++) acc[a][p] = 0ull;

        __syncthreads();   // previous tile's reads complete
        // ---- stage Cs (80 x 256, float4) ----
        for (int v = tid; v < 5120; v += 512) {
            int ci = v >> 6, jq = v & 63;
            *(float4*)(Us + ci * 256 + jq * 4) =
                *(const float4*)(c + ((b * 80 + ci) << 14) + t0 + jq * 4);
        }
        __syncthreads();

        // ---- conditioning GEMM (80 K) ----
#pragma unroll 2
        for (int ci = 0; ci < 80; ci++) {
            const float* wp = Wc_s + ci * 128 + G8;
            float4 wA = *(const float4*)(wp);
            float4 wB = *(const float4*)(wp + 4);
            ull w[8] = {pack2(wA.x), pack2(wA.y), pack2(wA.z), pack2(wA.w),
                        pack2(wB.x), pack2(wB.y), pack2(wB.z), pack2(wB.w)};
            const float* hp = Us + ci * 256 + TB;
            ulonglong2 hA = *(const ulonglong2*)(hp);
            ulonglong2 hB = *(const ulonglong2*)(hp + 4);
            ull hv[4] = {hA.x, hA.y, hB.x, hB.y};
#pragma unroll
            for (int a = 0; a < 8; a++)
#pragma unroll
                for (int p = 0; p < 4; p++)
                    fma2(acc[a][p], w[a], hv[p]);
        }

        // ---- 3 dilated taps, Hs staged per tap into Us ----
#pragma unroll 1
        for (int k = 0; k < 3; k++) {
            __syncthreads();  // previous phase's Us reads done
            int shift = (2 - k) * dil;
            if (t0 >= 1024 && (shift & 3) == 0) {
                // fast vector path: no boundary, aligned
                for (int v = tid; v < 4096; v += 512) {
                    int r = v >> 6, jq = v & 63;
                    *(float4*)(Us + r * 256 + jq * 4) =
                        *(const float4*)(h_in + ((b * 64 + r) << 14) + t0 + jq * 4 - shift);
                }
            } else {
                for (int v = tid; v < 16384; v += 512) {
                    int r = v >> 8, j = v & 255;
                    int t = t0 + j - shift;
                    Us[r * 256 + j] = (t >= 0) ? h_in[((b * 64 + r) << 14) + t] : 0.f;
                }
            }
            __syncthreads();

            const float* wbase = Wd_s + k * 128 + G8;
#pragma unroll 2
            for (int r = 0; r < 64; r++) {
                const float* wp = wbase + r * 384;
                float4 wA = *(const float4*)(wp);
                float4 wB = *(const float4*)(wp + 4);
                ull w[8] = {pack2(wA.x), pack2(wA.y), pack2(wA.z), pack2(wA.w),
                            pack2(wB.x), pack2(wB.y), pack2(wB.z), pack2(wB.w)};
                const float* hp = Us + r * 256 + TB;
                ulonglong2 hA = *(const ulonglong2*)(hp);
                ulonglong2 hB = *(const ulonglong2*)(hp + 4);
                ull hv[4] = {hA.x, hA.y, hB.x, hB.y};
#pragma unroll
                for (int a = 0; a < 8; a++)
#pragma unroll
                    for (int p = 0; p < 4; p++)
                        fma2(acc[a][p], w[a], hv[p]);
            }
        }

        // ---- epilogue: z = tanh(a)*sigmoid(b) in registers ----
        int m0 = G8 >> 1;
#pragma unroll
        for (int i = 0; i < 4; i++) {
            float ba = bs[G8 + 2 * i], bb = bs[G8 + 2 * i + 1];
            float zr[8];
#pragma unroll
            for (int p = 0; p < 4; p++) {
                float2 ya = unpack2(acc[2 * i][p]);
                float2 yb = unpack2(acc[2 * i + 1][p]);
                zr[2 * p]     = tanhf(ya.x + ba) * sigmoidf_(yb.x + bb);
                zr[2 * p + 1] = tanhf(ya.y + ba) * sigmoidf_(yb.y + bb);
            }
            float* zp = &g_z[((b * 64 + m0 + i) << 14) + t0 + TB];
            *(float4*)zp       = make_float4(zr[0], zr[1], zr[2], zr[3]);
            *(float4*)(zp + 4) = make_float4(zr[4], zr[5], zr[6], zr[7]);
        }
    }
}

// =======================================================================
// Kernel 3 (v3): skip + out. 2 CTAs/SM. (unchanged)
// =======================================================================
#define SKIPOUT_SMEM 99584
__global__ __launch_bounds__(512, 2) void skipout_kernel(
    int layer, int hsel,
    const float* __restrict__ W_skip, const float* __restrict__ b_skip,
    const float* __restrict__ W_out, const float* __restrict__ b_out)
{
    extern __shared__ float sm[];
    float* Wsk_s = sm;                  // r*256 + sc
    float* Wo_s  = Wsk_s + 16384;       // r*64 + oc
    float* bsk_s = Wo_s + 4096;         // 256
    float* bo_s  = bsk_s + 256;         // 64
    float* Zs    = bo_s + 64;           // r*64 + t

    int tid = threadIdx.x;
    const float* Wsk = W_skip + layer * 256 * 64;
    const float* Wo  = W_out + layer * 64 * 64;
    const float* h_in = g_h[hsel];
    float* h_out = g_h[1 - hsel];

    for (int i = tid; i < 256 * 64; i += 512) {
        int sc = i >> 6; int r = i & 63;
        Wsk_s[r * 256 + sc] = Wsk[i];
    }
    for (int i = tid; i < 64 * 64; i += 512) {
        int oc = i >> 6; int r = i & 63;
        Wo_s[r * 64 + oc] = Wo[i];
    }
    if (tid < 256) bsk_s[tid] = b_skip[layer * 256 + tid];
    if (tid < 64)  bo_s[tid]  = b_out[layer * 64 + tid];
    __syncthreads();

    int tq = tid & 7, grp = tid >> 3;   // grp 0..63
    int tb = tq * 8;
    int sc4 = grp * 4;
    int oc1 = grp;

    for (int tile = blockIdx.x; tile < NB * 256; tile += gridDim.x) {
        int b = tile >> 8;
        int t0 = (tile & 255) << 6;
        __syncthreads();
        for (int i = tid; i < 4096; i += 512) {
            int r = i >> 6; int j = i & 63;
            Zs[i] = g_z[((b * 64 + r) << 14) + t0 + j];
        }
        __syncthreads();

        ull accS[4][4];
        ull accO[4];
#pragma unroll
        for (int a = 0; a < 4; a++) {
            accO[a] = 0ull;
#pragma unroll
            for (int p = 0; p < 4; p++) accS[a][p] = 0ull;
        }

#pragma unroll 2
        for (int r = 0; r < 64; r++) {
            const float* zp = Zs + r * 64 + tb;
            ulonglong2 zA = *(const ulonglong2*)zp;
            ulonglong2 zB = *(const ulonglong2*)(zp + 4);
            float4 ws = *(const float4*)(Wsk_s + r * 256 + sc4);
            ull w0 = pack2(ws.x), w1 = pack2(ws.y), w2 = pack2(ws.z), w3 = pack2(ws.w);
            ull wo = pack2(Wo_s[r * 64 + oc1]);
            fma2(accS[0][0], w0, zA.x); fma2(accS[1][0], w1, zA.x);
            fma2(accS[2][0], w2, zA.x); fma2(accS[3][0], w3, zA.x);
            fma2(accO[0], wo, zA.x);
            fma2(accS[0][1], w0, zA.y); fma2(accS[1][1], w1, zA.y);
            fma2(accS[2][1], w2, zA.y); fma2(accS[3][1], w3, zA.y);
            fma2(accO[1], wo, zA.y);
            fma2(accS[0][2], w0, zB.x); fma2(accS[1][2], w1, zB.x);
            fma2(accS[2][2], w2, zB.x); fma2(accS[3][2], w3, zB.x);
            fma2(accO[2], wo, zB.x);
            fma2(accS[0][3], w0, zB.y); fma2(accS[1][3], w1, zB.y);
            fma2(accS[2][3], w2, zB.y); fma2(accS[3][3], w3, zB.y);
            fma2(accO[3], wo, zB.y);
        }

        // skip accumulate
#pragma unroll
        for (int a = 0; a < 4; a++) {
            int sc = sc4 + a;
            float bsv = bsk_s[sc];
            float2 q0 = unpack2(accS[a][0]);
            float2 q1 = unpack2(accS[a][1]);
            float2 q2 = unpack2(accS[a][2]);
            float2 q3 = unpack2(accS[a][3]);
            float* sp = &g_skip[((b * 256 + sc) << 14) + t0 + tb];
            if (layer == 0) {
                float4 v0 = make_float4(q0.x + bsv, q0.y + bsv, q1.x + bsv, q1.y + bsv);
                float4 v1 = make_float4(q2.x + bsv, q2.y + bsv, q3.x + bsv, q3.y + bsv);
                *(float4*)sp = v0;
                *(float4*)(sp + 4) = v1;
            } else {
                float4 o0 = *(const float4*)sp;
                float4 o1 = *(const float4*)(sp + 4);
                float4 v0, v1;
                v0.x = (o0.x + q0.x + bsv) * SQRT_HALF_F;
                v0.y = (o0.y + q0.y + bsv) * SQRT_HALF_F;
                v0.z = (o0.z + q1.x + bsv) * SQRT_HALF_F;
                v0.w = (o0.w + q1.y + bsv) * SQRT_HALF_F;
                v1.x = (o1.x + q2.x + bsv) * SQRT_HALF_F;
                v1.y = (o1.y + q2.y + bsv) * SQRT_HALF_F;
                v1.z = (o1.z + q3.x + bsv) * SQRT_HALF_F;
                v1.w = (o1.w + q3.y + bsv) * SQRT_HALF_F;
                *(float4*)sp = v0;
                *(float4*)(sp + 4) = v1;
            }
        }

        // residual update (1 out channel per thread)
        {
            float bov = bo_s[oc1];
            float2 q0 = unpack2(accO[0]);
            float2 q1 = unpack2(accO[1]);
            float2 q2 = unpack2(accO[2]);
            float2 q3 = unpack2(accO[3]);
            const float* hip = h_in + ((b * 64 + oc1) << 14) + t0 + tb;
            float* hop = h_out + ((b * 64 + oc1) << 14) + t0 + tb;
            float4 h0 = *(const float4*)hip;
            float4 h1 = *(const float4*)(hip + 4);
            float4 v0, v1;
            v0.x = (q0.x + bov + h0.x) * SQRT_HALF_F;
            v0.y = (q0.y + bov + h0.y) * SQRT_HALF_F;
            v0.z = (q1.x + bov + h0.z) * SQRT_HALF_F;
            v0.w = (q1.y + bov + h0.w) * SQRT_HALF_F;
            v1.x = (q2.x + bov + h1.x) * SQRT_HALF_F;
            v1.y = (q2.y + bov + h1.y) * SQRT_HALF_F;
            v1.z = (q3.x + bov + h1.z) * SQRT_HALF_F;
            v1.w = (q3.y + bov + h1.w) * SQRT_HALF_F;
            *(float4*)hop = v0;
            *(float4*)(hop + 4) = v1;
        }
    }
}

// =======================================================================
// Kernel 4 (v3): dense 256x256, W staged in 32-row chunks, 2 CTAs/SM.
// =======================================================================
#define DENSE_SMEM 99840
__global__ __launch_bounds__(512, 2) void dense256_kernel(
    int stage, float* __restrict__ final_out,
    const float* __restrict__ W, const float* __restrict__ bias)
{
    extern __shared__ float sm[];
    float* Ss = sm;             // sc*64 + t
    float* Wt = Ss + 16384;     // scc*260 + oc  (scc < 32)
    float* bb = Wt + 8320;      // 256

    const float* in = (stage == 0) ? g_skip : g_tmp;
    float* out = (stage == 0) ? g_tmp : final_out;

    int tid = threadIdx.x;
    if (tid < 256) bb[tid] = bias[tid];

    int tq = tid & 7, ocg = tid >> 3;
    int tb = tq * 8, oc4 = ocg * 4;

    for (int tile = blockIdx.x; tile < NB * 256; tile += gridDim.x) {
        int b = tile >> 8;
        int t0 = (tile & 255) << 6;

        __syncthreads();
        for (int i = tid; i < 16384; i += 512) {
            int sc = i >> 6, j = i & 63;
            float v = in[((b * 256 + sc) << 14) + t0 + j];
            if (stage == 0) v = fmaxf(v, 0.f);
            Ss[i] = v;
        }

        ull acc[4][4];
#pragma unroll
        for (int a = 0; a < 4; a++)
#pragma unroll
            for (int p = 0; p < 4; p++) acc[a][p] = 0ull;

        for (int c0 = 0; c0 < 256; c0 += 32) {
            __syncthreads();
            for (int i = tid; i < 32 * 256; i += 512) {
                int scc = i & 31, oc = i >> 5;
                Wt[scc * 260 + oc] = W[oc * 256 + c0 + scc];
            }
            __syncthreads();
#pragma unroll 4
            for (int scc = 0; scc < 32; scc++) {
                const float* sp = Ss + (c0 + scc) * 64 + tb;
                ulonglong2 zA = *(const ulonglong2*)sp;
                ulonglong2 zB = *(const ulonglong2*)(sp + 4);
                float4 w = *(const float4*)(Wt + scc * 260 + oc4);
                ull w0 = pack2(w.x), w1 = pack2(w.y), w2 = pack2(w.z), w3 = pack2(w.w);
                fma2(acc[0][0], w0, zA.x); fma2(acc[1][0], w1, zA.x);
                fma2(acc[2][0], w2, zA.x); fma2(acc[3][0], w3, zA.x);
                fma2(acc[0][1], w0, zA.y); fma2(acc[1][1], w1, zA.y);
                fma2(acc[2][1], w2, zA.y); fma2(acc[3][1], w3, zA.y);
                fma2(acc[0][2], w0, zB.x); fma2(acc[1][2], w1, zB.x);
                fma2(acc[2][2], w2, zB.x); fma2(acc[3][2], w3, zB.x);
                fma2(acc[0][3], w0, zB.y); fma2(acc[1][3], w1, zB.y);
                fma2(acc[2][3], w2, zB.y); fma2(acc[3][3], w3, zB.y);
            }
        }

#pragma unroll
        for (int a = 0; a < 4; a++) {
            int oc = oc4 + a;
            float bv = bb[oc];
            float2 q0 = unpack2(acc[a][0]);
            float2 q1 = unpack2(acc[a][1]);
            float2 q2 = unpack2(acc[a][2]);
            float2 q3 = unpack2(acc[a][3]);
            float* op = out + ((b * 256 + oc) << 14) + t0 + tb;
            float4 v0 = make_float4(q0.x + bv, q0.y + bv, q1.x + bv, q1.y + bv);
            float4 v1 = make_float4(q2.x + bv, q2.y + bv, q3.x + bv, q3.y + bv);
            if (stage == 0) {
                v0.x = fmaxf(v0.x, 0.f); v0.y = fmaxf(v0.y, 0.f);
                v0.z = fmaxf(v0.z, 0.f); v0.w = fmaxf(v0.w, 0.f);
                v1.x = fmaxf(v1.x, 0.f); v1.y = fmaxf(v1.y, 0.f);
                v1.z = fmaxf(v1.z, 0.f); v1.w = fmaxf(v1.w, 0.f);
            }
            *(float4*)op = v0;
            *(float4*)(op + 4) = v1;
        }
    }
}

// =======================================================================
extern "C" void kernel_launch(void* const* d_in, const int* in_sizes, int n_in,
                              void* d_out, int out_size)
{
    const float* x       = (const float*)d_in[0];
    const float* c       = (const float*)d_in[1];
    const float* W_first = (const float*)d_in[2];
    const float* b_first = (const float*)d_in[3];
    const float* W_dil   = (const float*)d_in[4];
    const float* b_dil   = (const float*)d_in[5];
    const float* W_c     = (const float*)d_in[6];
    const float* b_c     = (const float*)d_in[7];
    const float* W_skip  = (const float*)d_in[8];
    const float* b_skip  = (const float*)d_in[9];
    const float* W_out   = (const float*)d_in[10];
    const float* b_out   = (const float*)d_in[11];
    const float* W_last1 = (const float*)d_in[12];
    const float* b_last1 = (const float*)d_in[13];
    const float* W_last2 = (const float*)d_in[14];
    const float* b_last2 = (const float*)d_in[15];
    float* out = (float*)d_out;

    cudaFuncSetAttribute(first_kernel,  cudaFuncAttributeMaxDynamicSharedMemorySize, FIRST_SMEM);
    cudaFuncSetAttribute(gate_kernel,   cudaFuncAttributeMaxDynamicSharedMemorySize, GATE_SMEM);
    cudaFuncSetAttribute(skipout_kernel,cudaFuncAttributeMaxDynamicSharedMemorySize, SKIPOUT_SMEM);
    cudaFuncSetAttribute(dense256_kernel,cudaFuncAttributeMaxDynamicSharedMemorySize, DENSE_SMEM);

    int dev = 0;
    cudaGetDevice(&dev);
    int sm_count = 148;
    cudaDeviceGetAttribute(&sm_count, cudaDevAttrMultiProcessorCount, dev);
    int grid1 = sm_count;
    int grid2 = 2 * sm_count;

    first_kernel<<<grid1, 256, FIRST_SMEM>>>(x, W_first, b_first);

    for (int l = 0; l < 20; l++) {
        int dil = 1 << (l % 10);
        int hsel = l & 1;   // layer l reads g_h[hsel], writes g_h[1-hsel]
        gate_kernel<<<grid1, 512, GATE_SMEM>>>(l, dil, hsel, c,
                                               W_dil, b_dil, W_c, b_c);
        skipout_kernel<<<grid2, 512, SKIPOUT_SMEM>>>(l, hsel,
                                                     W_skip, b_skip, W_out, b_out);
    }

    dense256_kernel<<<grid2, 512, DENSE_SMEM>>>(0, out, W_last1, b_last1);
    dense256_kernel<<<grid2, 512, DENSE_SMEM>>>(1, out, W_last2, b_last2);
}

// round 7
// speedup vs baseline: 1.2907x; 1.2267x over previous
#include <cuda_runtime.h>
#include <cuda_bf16.h>
#include <stdint.h>
#include <math.h>

#define T_LEN 16384
#define NB 4

static __device__ __forceinline__ float sigmoidf_(float v) {
    return 1.0f / (1.0f + __expf(-v));
}

#define SQRT_HALF_F 0.70710678118654752f

typedef unsigned long long ull;

// packed f32x2 helpers (skipout/dense kernels)
static __device__ __forceinline__ ull pack2(float v) {
    ull r;
    asm("mov.b64 %0, {%1, %1};" : "=l"(r) : "f"(v));
    return r;
}
static __device__ __forceinline__ void fma2(ull& d, ull a, ull b) {
    asm("fma.rn.f32x2 %0, %1, %2, %0;" : "+l"(d) : "l"(a), "l"(b));
}
static __device__ __forceinline__ float2 unpack2(ull v) {
    float2 r;
    asm("mov.b64 {%0, %1}, %2;" : "=f"(r.x), "=f"(r.y) : "l"(v));
    return r;
}

// bf16 HMMA m16n8k16 (base-target PTX, works on sm_103 non-'a')
static __device__ __forceinline__ void mma_bf16(
    float* d, uint32_t a0, uint32_t a1, uint32_t a2, uint32_t a3,
    uint32_t b0, uint32_t b1)
{
    asm volatile(
        "mma.sync.aligned.m16n8k16.row.col.f32.bf16.bf16.f32 "
        "{%0,%1,%2,%3}, {%4,%5,%6,%7}, {%8,%9}, {%0,%1,%2,%3};"
        : "+f"(d[0]), "+f"(d[1]), "+f"(d[2]), "+f"(d[3])
        : "r"(a0), "r"(a1), "r"(a2), "r"(a3), "r"(b0), "r"(b1));
}
static __device__ __forceinline__ uint32_t pk_bf2(float a, float b) {
    __nv_bfloat162 t;
    t.x = __float2bfloat16(a);
    t.y = __float2bfloat16(b);
    return *(uint32_t*)&t;
}

// ---------------- scratch (allocation-free: __device__ globals) ----------------
__device__ float g_h[2][NB * 64 * T_LEN];     // residual ping-pong
__device__ float g_z[NB * 64 * T_LEN];        // gated activations per layer
__device__ float g_skip[NB * 256 * T_LEN];    // skip accumulator
__device__ float g_tmp[NB * 256 * T_LEN];     // final intermediate

// =======================================================================
// Kernel 1: first conv (k=2 causal, 256 -> 64) + tanh. (unchanged)
// =======================================================================
#define FIRST_SMEM 200960
__global__ __launch_bounds__(256) void first_kernel(
    const float* __restrict__ x, const float* __restrict__ Wf,
    const float* __restrict__ bf)
{
    extern __shared__ float sm[];
    float* Wf_s = sm;
    float* bs   = Wf_s + 32768;
    float* Xs   = bs + 64;

    int tid = threadIdx.x;
    for (int i = tid; i < 64 * 256 * 2; i += 256) {
        int oc = i >> 9; int ic = (i >> 1) & 255; int k = i & 1;
        Wf_s[ic * 128 + k * 64 + oc] = Wf[i];
    }
    if (tid < 64) bs[tid] = bf[tid];
    __syncthreads();

    int tq = tid & 7, grp = tid >> 3;
    int tb = tq * 8, oc2 = grp * 2;

    for (int tile = blockIdx.x; tile < NB * 256; tile += gridDim.x) {
        int b = tile >> 8;
        int t0 = (tile & 255) << 6;
        __syncthreads();
        for (int i = tid; i < 256 * 65; i += 256) {
            int ic = i / 65, jj = i - ic * 65;
            int t = (jj < 64) ? (t0 + jj) : (t0 - 1);
            Xs[ic * 68 + jj] = (t >= 0) ? x[((b * 256 + ic) << 14) + t] : 0.f;
        }
        __syncthreads();

        float acc[2][8];
#pragma unroll
        for (int a = 0; a < 2; a++)
#pragma unroll
            for (int j = 0; j < 8; j++) acc[a][j] = 0.f;

#pragma unroll 2
        for (int ic = 0; ic < 256; ic++) {
            const float* xp = Xs + ic * 68 + tb;
            float4 x0 = *(const float4*)xp;
            float4 x1 = *(const float4*)(xp + 4);
            float xm1 = (tb == 0) ? Xs[ic * 68 + 64] : Xs[ic * 68 + tb - 1];
            float2 w0 = *(const float2*)(Wf_s + ic * 128 + oc2);
            float2 w1 = *(const float2*)(Wf_s + ic * 128 + 64 + oc2);
            float xc[8] = {x0.x, x0.y, x0.z, x0.w, x1.x, x1.y, x1.z, x1.w};
            float xpv[8] = {xm1, xc[0], xc[1], xc[2], xc[3], xc[4], xc[5], xc[6]};
            float wa[2] = {w0.x, w0.y};
            float wb[2] = {w1.x, w1.y};
#pragma unroll
            for (int a = 0; a < 2; a++)
#pragma unroll
                for (int j = 0; j < 8; j++)
                    acc[a][j] += wa[a] * xpv[j] + wb[a] * xc[j];
        }

#pragma unroll
        for (int a = 0; a < 2; a++) {
            int oc = oc2 + a;
            float bv = bs[oc];
            float* hp = &g_h[0][((b * 64 + oc) << 14) + t0 + tb];
            float4 v0, v1;
            v0.x = tanhf(acc[a][0] + bv); v0.y = tanhf(acc[a][1] + bv);
            v0.z = tanhf(acc[a][2] + bv); v0.w = tanhf(acc[a][3] + bv);
            v1.x = tanhf(acc[a][4] + bv); v1.y = tanhf(acc[a][5] + bv);
            v1.z = tanhf(acc[a][6] + bv); v1.w = tanhf(acc[a][7] + bv);
            *(float4*)hp = v0;
            *(float4*)(hp + 4) = v1;
        }
    }
}

// =======================================================================
// Kernel 2 (v6 — HMMA): gate via mma.sync bf16 hi/lo split (3 passes).
//   D[pg][n] = sum_k A[pg][k]*B[n][k]; M=128 perm gates, N=128 t, K=272.
// Warp w: m0=(w&7)*16, n-half=(w>>3)*64 -> 8 n-tiles of 8, accs in regs.
// SMEM (bytes):
//   0      : bias 128 f (512)
//   1024   : A_hi bf16 [128][280]  (71680)
//   72704  : A_lo bf16 [128][280]  (71680)
//   144384 : B_hi bf16 [128][152]  (38912)   \ reused as ys[128][132] f32
//   183296 : B_lo bf16 [128][152]  (38912)   /   after MMA
//   total 222208
// K chunks: 0..143 (9 ksteps), 144..271 (8 ksteps); B staged per chunk.
// =======================================================================
#define GATE_SMEM 222208
__global__ __launch_bounds__(512) void gate_kernel(
    int layer, int dil, int hsel,
    const float* __restrict__ c,
    const float* __restrict__ W_dil, const float* __restrict__ b_dil,
    const float* __restrict__ W_c, const float* __restrict__ b_c)
{
    extern __shared__ float smf[];
    char* smem = (char*)smf;

    int tid = threadIdx.x;
    int lane = tid & 31, warp = tid >> 5;
    const float* Wd = W_dil + layer * 24576;
    const float* Wc = W_c + layer * 10240;
    const float* h_in = g_h[hsel];

    __nv_bfloat16* Ah_s = (__nv_bfloat16*)(smem + 1024);
    __nv_bfloat16* Al_s = (__nv_bfloat16*)(smem + 72704);
    __nv_bfloat16* Bh_s = (__nv_bfloat16*)(smem + 144384);
    __nv_bfloat16* Bl_s = (__nv_bfloat16*)(smem + 183296);
    float* ys = (float*)(smem + 144384);    // overlay on B region

    if (tid < 128) {   // bias, permuted-gate indexed
        int g = (tid & 1) ? 64 + (tid >> 1) : (tid >> 1);
        smf[tid] = b_dil[layer * 128 + g] + b_c[layer * 128 + g];
    }
    // ---- stage A (weights, hi/lo bf16), once per layer ----
    for (int i = tid; i < 128 * 272; i += 512) {
        int pg = i / 272, k = i - pg * 272;
        int g = (pg & 1) ? 64 + (pg >> 1) : (pg >> 1);
        float w = (k < 192) ? Wd[g * 192 + (k & 63) * 3 + (k >> 6)]
                            : Wc[g * 80 + (k - 192)];
        __nv_bfloat16 wh = __float2bfloat16(w);
        Ah_s[pg * 280 + k] = wh;
        Al_s[pg * 280 + k] = __float2bfloat16(w - __bfloat162float(wh));
    }
    __syncthreads();

    int m0 = (warp & 7) * 16;
    int n0 = (warp >> 3) * 64;
    int r0 = m0 + (lane >> 2);
    int q = (lane & 3) * 2;

    for (int tile = blockIdx.x; tile < NB * 128; tile += gridDim.x) {
        int b = tile >> 7;
        int t0 = (tile & 127) << 7;

        float d[8][4];
#pragma unroll
        for (int nt = 0; nt < 8; nt++)
#pragma unroll
            for (int e = 0; e < 4; e++) d[nt][e] = 0.f;

#pragma unroll 1
        for (int chunk = 0; chunk < 2; chunk++) {
            // ---- stage B chunk (hi/lo): k-groups [ug0, ug1) x 4 n-blocks ----
            int ug0 = chunk ? 18 : 0;
            int ug1 = chunk ? 34 : 18;
            for (int u = ug0 * 4 + warp; u < ug1 * 4; u += 16) {
                int kg = u >> 2, nb = u & 3;
                int n = (nb << 5) + lane;
                int t = t0 + n;
                float v[8];
                if (kg < 24) {
                    int tap = kg >> 3, rb = (kg & 7) << 3;
                    int ts = t - (2 - tap) * dil;
                    const float* hp = h_in + ((b * 64 + rb) << 14) + ts;
                    if (ts >= 0) {
#pragma unroll
                        for (int j = 0; j < 8; j++) v[j] = hp[j << 14];
                    } else {
#pragma unroll
                        for (int j = 0; j < 8; j++) v[j] = 0.f;
                    }
                } else {
                    int cb = (kg - 24) << 3;
                    const float* cp = c + ((b * 80 + cb) << 14) + t;
#pragma unroll
                    for (int j = 0; j < 8; j++) v[j] = cp[j << 14];
                }
                uint32_t ph[4], pl[4];
#pragma unroll
                for (int m = 0; m < 4; m++) {
                    float a0 = v[2 * m], a1 = v[2 * m + 1];
                    __nv_bfloat16 h0 = __float2bfloat16(a0);
                    __nv_bfloat16 h1 = __float2bfloat16(a1);
                    ph[m] = pk_bf2(a0, a1);
                    pl[m] = pk_bf2(a0 - __bfloat162float(h0),
                                   a1 - __bfloat162float(h1));
                }
                int klocal = kg * 8 - (chunk ? 144 : 0);
                *(uint4*)(Bh_s + n * 152 + klocal) = make_uint4(ph[0], ph[1], ph[2], ph[3]);
                *(uint4*)(Bl_s + n * 152 + klocal) = make_uint4(pl[0], pl[1], pl[2], pl[3]);
            }
            __syncthreads();

            // ---- HMMA: 3 passes over this chunk's ksteps ----
            int nk = chunk ? 8 : 9;
            int kAbase = chunk ? 144 : 0;
#pragma unroll 1
            for (int pass = 0; pass < 3; pass++) {
                const __nv_bfloat16* Ab = (pass == 2) ? Al_s : Ah_s;
                const __nv_bfloat16* Bb = (pass == 1) ? Bl_s : Bh_s;
#pragma unroll 1
                for (int ks = 0; ks < nk; ks++) {
                    int kA = kAbase + ks * 16;
                    int kB = ks * 16;
                    uint32_t a0 = *(const uint32_t*)(Ab + r0 * 280 + kA + q);
                    uint32_t a1 = *(const uint32_t*)(Ab + (r0 + 8) * 280 + kA + q);
                    uint32_t a2 = *(const uint32_t*)(Ab + r0 * 280 + kA + 8 + q);
                    uint32_t a3 = *(const uint32_t*)(Ab + (r0 + 8) * 280 + kA + 8 + q);
#pragma unroll
                    for (int nt = 0; nt < 8; nt++) {
                        int n = n0 + nt * 8 + (lane >> 2);
                        uint32_t b0 = *(const uint32_t*)(Bb + n * 152 + kB + q);
                        uint32_t b1 = *(const uint32_t*)(Bb + n * 152 + kB + 8 + q);
                        mma_bf16(d[nt], a0, a1, a2, a3, b0, b1);
                    }
                }
            }
            __syncthreads();   // all B reads done before restage / ys overlay
        }

        // ---- dump accumulators to ys[pg][n] (B region is dead now) ----
#pragma unroll
        for (int nt = 0; nt < 8; nt++) {
            int col = n0 + nt * 8 + q;
            *(float2*)(ys + r0 * 132 + col)       = make_float2(d[nt][0], d[nt][1]);
            *(float2*)(ys + (r0 + 8) * 132 + col) = make_float2(d[nt][2], d[nt][3]);
        }
        __syncthreads();

        // ---- z = tanh(a)*sigmoid(b): all 512 threads, 16 z each ----
        {
            int i = tid >> 3;        // gate channel 0..63
            int qb = tid & 7;        // 16-col block
            float ba = smf[2 * i], bb = smf[2 * i + 1];
            const float* ya = ys + (2 * i) * 132 + qb * 16;
            const float* yb = ys + (2 * i + 1) * 132 + qb * 16;
            float* zp = &g_z[((b * 64 + i) << 14) + t0 + qb * 16];
#pragma unroll
            for (int e = 0; e < 4; e++) {
                float4 av = *(const float4*)(ya + e * 4);
                float4 bv = *(const float4*)(yb + e * 4);
                float4 zv;
                zv.x = tanhf(av.x + ba) * sigmoidf_(bv.x + bb);
                zv.y = tanhf(av.y + ba) * sigmoidf_(bv.y + bb);
                zv.z = tanhf(av.z + ba) * sigmoidf_(bv.z + bb);
                zv.w = tanhf(av.w + ba) * sigmoidf_(bv.w + bb);
                *(float4*)(zp + e * 4) = zv;
            }
        }
        __syncthreads();   // ys reads done before next tile stages B
    }
}

// =======================================================================
// Kernel 3 (v3): skip + out. 2 CTAs/SM. (unchanged)
// =======================================================================
#define SKIPOUT_SMEM 99584
__global__ __launch_bounds__(512, 2) void skipout_kernel(
    int layer, int hsel,
    const float* __restrict__ W_skip, const float* __restrict__ b_skip,
    const float* __restrict__ W_out, const float* __restrict__ b_out)
{
    extern __shared__ float sm[];
    float* Wsk_s = sm;
    float* Wo_s  = Wsk_s + 16384;
    float* bsk_s = Wo_s + 4096;
    float* bo_s  = bsk_s + 256;
    float* Zs    = bo_s + 64;

    int tid = threadIdx.x;
    const float* Wsk = W_skip + layer * 256 * 64;
    const float* Wo  = W_out + layer * 64 * 64;
    const float* h_in = g_h[hsel];
    float* h_out = g_h[1 - hsel];

    for (int i = tid; i < 256 * 64; i += 512) {
        int sc = i >> 6; int r = i & 63;
        Wsk_s[r * 256 + sc] = Wsk[i];
    }
    for (int i = tid; i < 64 * 64; i += 512) {
        int oc = i >> 6; int r = i & 63;
        Wo_s[r * 64 + oc] = Wo[i];
    }
    if (tid < 256) bsk_s[tid] = b_skip[layer * 256 + tid];
    if (tid < 64)  bo_s[tid]  = b_out[layer * 64 + tid];
    __syncthreads();

    int tq = tid & 7, grp = tid >> 3;
    int tb = tq * 8;
    int sc4 = grp * 4;
    int oc1 = grp;

    for (int tile = blockIdx.x; tile < NB * 256; tile += gridDim.x) {
        int b = tile >> 8;
        int t0 = (tile & 255) << 6;
        __syncthreads();
        for (int i = tid; i < 4096; i += 512) {
            int r = i >> 6; int j = i & 63;
            Zs[i] = g_z[((b * 64 + r) << 14) + t0 + j];
        }
        __syncthreads();

        ull accS[4][4];
        ull accO[4];
#pragma unroll
        for (int a = 0; a < 4; a++) {
            accO[a] = 0ull;
#pragma unroll
            for (int p = 0; p < 4; p++) accS[a][p] = 0ull;
        }

#pragma unroll 2
        for (int r = 0; r < 64; r++) {
            const float* zp = Zs + r * 64 + tb;
            ulonglong2 zA = *(const ulonglong2*)zp;
            ulonglong2 zB = *(const ulonglong2*)(zp + 4);
            float4 ws = *(const float4*)(Wsk_s + r * 256 + sc4);
            ull w0 = pack2(ws.x), w1 = pack2(ws.y), w2 = pack2(ws.z), w3 = pack2(ws.w);
            ull wo = pack2(Wo_s[r * 64 + oc1]);
            fma2(accS[0][0], w0, zA.x); fma2(accS[1][0], w1, zA.x);
            fma2(accS[2][0], w2, zA.x); fma2(accS[3][0], w3, zA.x);
            fma2(accO[0], wo, zA.x);
            fma2(accS[0][1], w0, zA.y); fma2(accS[1][1], w1, zA.y);
            fma2(accS[2][1], w2, zA.y); fma2(accS[3][1], w3, zA.y);
            fma2(accO[1], wo, zA.y);
            fma2(accS[0][2], w0, zB.x); fma2(accS[1][2], w1, zB.x);
            fma2(accS[2][2], w2, zB.x); fma2(accS[3][2], w3, zB.x);
            fma2(accO[2], wo, zB.x);
            fma2(accS[0][3], w0, zB.y); fma2(accS[1][3], w1, zB.y);
            fma2(accS[2][3], w2, zB.y); fma2(accS[3][3], w3, zB.y);
            fma2(accO[3], wo, zB.y);
        }

#pragma unroll
        for (int a = 0; a < 4; a++) {
            int sc = sc4 + a;
            float bsv = bsk_s[sc];
            float2 q0 = unpack2(accS[a][0]);
            float2 q1 = unpack2(accS[a][1]);
            float2 q2 = unpack2(accS[a][2]);
            float2 q3 = unpack2(accS[a][3]);
            float* sp = &g_skip[((b * 256 + sc) << 14) + t0 + tb];
            if (layer == 0) {
                float4 v0 = make_float4(q0.x + bsv, q0.y + bsv, q1.x + bsv, q1.y + bsv);
                float4 v1 = make_float4(q2.x + bsv, q2.y + bsv, q3.x + bsv, q3.y + bsv);
                *(float4*)sp = v0;
                *(float4*)(sp + 4) = v1;
            } else {
                float4 o0 = *(const float4*)sp;
                float4 o1 = *(const float4*)(sp + 4);
                float4 v0, v1;
                v0.x = (o0.x + q0.x + bsv) * SQRT_HALF_F;
                v0.y = (o0.y + q0.y + bsv) * SQRT_HALF_F;
                v0.z = (o0.z + q1.x + bsv) * SQRT_HALF_F;
                v0.w = (o0.w + q1.y + bsv) * SQRT_HALF_F;
                v1.x = (o1.x + q2.x + bsv) * SQRT_HALF_F;
                v1.y = (o1.y + q2.y + bsv) * SQRT_HALF_F;
                v1.z = (o1.z + q3.x + bsv) * SQRT_HALF_F;
                v1.w = (o1.w + q3.y + bsv) * SQRT_HALF_F;
                *(float4*)sp = v0;
                *(float4*)(sp + 4) = v1;
            }
        }

        {
            float bov = bo_s[oc1];
            float2 q0 = unpack2(accO[0]);
            float2 q1 = unpack2(accO[1]);
            float2 q2 = unpack2(accO[2]);
            float2 q3 = unpack2(accO[3]);
            const float* hip = h_in + ((b * 64 + oc1) << 14) + t0 + tb;
            float* hop = h_out + ((b * 64 + oc1) << 14) + t0 + tb;
            float4 h0 = *(const float4*)hip;
            float4 h1 = *(const float4*)(hip + 4);
            float4 v0, v1;
            v0.x = (q0.x + bov + h0.x) * SQRT_HALF_F;
            v0.y = (q0.y + bov + h0.y) * SQRT_HALF_F;
            v0.z = (q1.x + bov + h0.z) * SQRT_HALF_F;
            v0.w = (q1.y + bov + h0.w) * SQRT_HALF_F;
            v1.x = (q2.x + bov + h1.x) * SQRT_HALF_F;
            v1.y = (q2.y + bov + h1.y) * SQRT_HALF_F;
            v1.z = (q3.x + bov + h1.z) * SQRT_HALF_F;
            v1.w = (q3.y + bov + h1.w) * SQRT_HALF_F;
            *(float4*)hop = v0;
            *(float4*)(hop + 4) = v1;
        }
    }
}

// =======================================================================
// Kernel 4 (v3): dense 256x256, W staged in 32-row chunks, 2 CTAs/SM.
// =======================================================================
#define DENSE_SMEM 99840
__global__ __launch_bounds__(512, 2) void dense256_kernel(
    int stage, float* __restrict__ final_out,
    const float* __restrict__ W, const float* __restrict__ bias)
{
    extern __shared__ float sm[];
    float* Ss = sm;
    float* Wt = Ss + 16384;
    float* bb = Wt + 8320;

    const float* in = (stage == 0) ? g_skip : g_tmp;
    float* out = (stage == 0) ? g_tmp : final_out;

    int tid = threadIdx.x;
    if (tid < 256) bb[tid] = bias[tid];

    int tq = tid & 7, ocg = tid >> 3;
    int tb = tq * 8, oc4 = ocg * 4;

    for (int tile = blockIdx.x; tile < NB * 256; tile += gridDim.x) {
        int b = tile >> 8;
        int t0 = (tile & 255) << 6;

        __syncthreads();
        for (int i = tid; i < 16384; i += 512) {
            int sc = i >> 6, j = i & 63;
            float v = in[((b * 256 + sc) << 14) + t0 + j];
            if (stage == 0) v = fmaxf(v, 0.f);
            Ss[i] = v;
        }

        ull acc[4][4];
#pragma unroll
        for (int a = 0; a < 4; a++)
#pragma unroll
            for (int p = 0; p < 4; p++) acc[a][p] = 0ull;

        for (int c0 = 0; c0 < 256; c0 += 32) {
            __syncthreads();
            for (int i = tid; i < 32 * 256; i += 512) {
                int scc = i & 31, oc = i >> 5;
                Wt[scc * 260 + oc] = W[oc * 256 + c0 + scc];
            }
            __syncthreads();
#pragma unroll 4
            for (int scc = 0; scc < 32; scc++) {
                const float* sp = Ss + (c0 + scc) * 64 + tb;
                ulonglong2 zA = *(const ulonglong2*)sp;
                ulonglong2 zB = *(const ulonglong2*)(sp + 4);
                float4 w = *(const float4*)(Wt + scc * 260 + oc4);
                ull w0 = pack2(w.x), w1 = pack2(w.y), w2 = pack2(w.z), w3 = pack2(w.w);
                fma2(acc[0][0], w0, zA.x); fma2(acc[1][0], w1, zA.x);
                fma2(acc[2][0], w2, zA.x); fma2(acc[3][0], w3, zA.x);
                fma2(acc[0][1], w0, zA.y); fma2(acc[1][1], w1, zA.y);
                fma2(acc[2][1], w2, zA.y); fma2(acc[3][1], w3, zA.y);
                fma2(acc[0][2], w0, zB.x); fma2(acc[1][2], w1, zB.x);
                fma2(acc[2][2], w2, zB.x); fma2(acc[3][2], w3, zB.x);
                fma2(acc[0][3], w0, zB.y); fma2(acc[1][3], w1, zB.y);
                fma2(acc[2][3], w2, zB.y); fma2(acc[3][3], w3, zB.y);
            }
        }

#pragma unroll
        for (int a = 0; a < 4; a++) {
            int oc = oc4 + a;
            float bv = bb[oc];
            float2 q0 = unpack2(acc[a][0]);
            float2 q1 = unpack2(acc[a][1]);
            float2 q2 = unpack2(acc[a][2]);
            float2 q3 = unpack2(acc[a][3]);
            float* op = out + ((b * 256 + oc) << 14) + t0 + tb;
            float4 v0 = make_float4(q0.x + bv, q0.y + bv, q1.x + bv, q1.y + bv);
            float4 v1 = make_float4(q2.x + bv, q2.y + bv, q3.x + bv, q3.y + bv);
            if (stage == 0) {
                v0.x = fmaxf(v0.x, 0.f); v0.y = fmaxf(v0.y, 0.f);
                v0.z = fmaxf(v0.z, 0.f); v0.w = fmaxf(v0.w, 0.f);
                v1.x = fmaxf(v1.x, 0.f); v1.y = fmaxf(v1.y, 0.f);
                v1.z = fmaxf(v1.z, 0.f); v1.w = fmaxf(v1.w, 0.f);
            }
            *(float4*)op = v0;
            *(float4*)(op + 4) = v1;
        }
    }
}

// =======================================================================
extern "C" void kernel_launch(void* const* d_in, const int* in_sizes, int n_in,
                              void* d_out, int out_size)
{
    const float* x       = (const float*)d_in[0];
    const float* c       = (const float*)d_in[1];
    const float* W_first = (const float*)d_in[2];
    const float* b_first = (const float*)d_in[3];
    const float* W_dil   = (const float*)d_in[4];
    const float* b_dil   = (const float*)d_in[5];
    const float* W_c     = (const float*)d_in[6];
    const float* b_c     = (const float*)d_in[7];
    const float* W_skip  = (const float*)d_in[8];
    const float* b_skip  = (const float*)d_in[9];
    const float* W_out   = (const float*)d_in[10];
    const float* b_out   = (const float*)d_in[11];
    const float* W_last1 = (const float*)d_in[12];
    const float* b_last1 = (const float*)d_in[13];
    const float* W_last2 = (const float*)d_in[14];
    const float* b_last2 = (const float*)d_in[15];
    float* out = (float*)d_out;

    cudaFuncSetAttribute(first_kernel,  cudaFuncAttributeMaxDynamicSharedMemorySize, FIRST_SMEM);
    cudaFuncSetAttribute(gate_kernel,   cudaFuncAttributeMaxDynamicSharedMemorySize, GATE_SMEM);
    cudaFuncSetAttribute(skipout_kernel,cudaFuncAttributeMaxDynamicSharedMemorySize, SKIPOUT_SMEM);
    cudaFuncSetAttribute(dense256_kernel,cudaFuncAttributeMaxDynamicSharedMemorySize, DENSE_SMEM);

    int dev = 0;
    cudaGetDevice(&dev);
    int sm_count = 148;
    cudaDeviceGetAttribute(&sm_count, cudaDevAttrMultiProcessorCount, dev);
    int grid1 = sm_count;
    int grid2 = 2 * sm_count;

    first_kernel<<<grid1, 256, FIRST_SMEM>>>(x, W_first, b_first);

    for (int l = 0; l < 20; l++) {
        int dil = 1 << (l % 10);
        int hsel = l & 1;   // layer l reads g_h[hsel], writes g_h[1-hsel]
        gate_kernel<<<grid1, 512, GATE_SMEM>>>(l, dil, hsel, c,
                                               W_dil, b_dil, W_c, b_c);
        skipout_kernel<<<grid2, 512, SKIPOUT_SMEM>>>(l, hsel,
                                                     W_skip, b_skip, W_out, b_out);
    }

    dense256_kernel<<<grid2, 512, DENSE_SMEM>>>(0, out, W_last1, b_last1);
    dense256_kernel<<<grid2, 512, DENSE_SMEM>>>(1, out, W_last2, b_last2);
}

// round 8
// speedup vs baseline: 1.5367x; 1.1906x over previous
#include <cuda_runtime.h>
#include <cuda_bf16.h>
#include <stdint.h>
#include <math.h>

#define T_LEN 16384
#define NB 4

static __device__ __forceinline__ float sigmoidf_(float v) {
    return 1.0f / (1.0f + __expf(-v));
}

#define SQRT_HALF_F 0.70710678118654752f

typedef unsigned long long ull;

// packed f32x2 helpers (dense kernel)
static __device__ __forceinline__ ull pack2(float v) {
    ull r;
    asm("mov.b64 %0, {%1, %1};" : "=l"(r) : "f"(v));
    return r;
}
static __device__ __forceinline__ void fma2(ull& d, ull a, ull b) {
    asm("fma.rn.f32x2 %0, %1, %2, %0;" : "+l"(d) : "l"(a), "l"(b));
}
static __device__ __forceinline__ float2 unpack2(ull v) {
    float2 r;
    asm("mov.b64 {%0, %1}, %2;" : "=f"(r.x), "=f"(r.y) : "l"(v));
    return r;
}

// bf16 HMMA m16n8k16 (base-target PTX, works on sm_103 non-'a')
static __device__ __forceinline__ void mma_bf16(
    float* d, uint32_t a0, uint32_t a1, uint32_t a2, uint32_t a3,
    uint32_t b0, uint32_t b1)
{
    asm volatile(
        "mma.sync.aligned.m16n8k16.row.col.f32.bf16.bf16.f32 "
        "{%0,%1,%2,%3}, {%4,%5,%6,%7}, {%8,%9}, {%0,%1,%2,%3};"
        : "+f"(d[0]), "+f"(d[1]), "+f"(d[2]), "+f"(d[3])
        : "r"(a0), "r"(a1), "r"(a2), "r"(a3), "r"(b0), "r"(b1));
}
static __device__ __forceinline__ uint32_t pk_bf2(float a, float b) {
    __nv_bfloat162 t;
    t.x = __float2bfloat16(a);
    t.y = __float2bfloat16(b);
    return *(uint32_t*)&t;
}

// ---------------- scratch (allocation-free: __device__ globals) ----------------
__device__ float g_h[2][NB * 64 * T_LEN];     // residual ping-pong
__device__ float g_z[NB * 64 * T_LEN];        // gated activations per layer
__device__ float g_skip[NB * 256 * T_LEN];    // skip accumulator
__device__ float g_tmp[NB * 256 * T_LEN];     // final intermediate

// =======================================================================
// Kernel 1: first conv (k=2 causal, 256 -> 64) + tanh. (unchanged)
// =======================================================================
#define FIRST_SMEM 200960
__global__ __launch_bounds__(256) void first_kernel(
    const float* __restrict__ x, const float* __restrict__ Wf,
    const float* __restrict__ bf)
{
    extern __shared__ float sm[];
    float* Wf_s = sm;
    float* bs   = Wf_s + 32768;
    float* Xs   = bs + 64;

    int tid = threadIdx.x;
    for (int i = tid; i < 64 * 256 * 2; i += 256) {
        int oc = i >> 9; int ic = (i >> 1) & 255; int k = i & 1;
        Wf_s[ic * 128 + k * 64 + oc] = Wf[i];
    }
    if (tid < 64) bs[tid] = bf[tid];
    __syncthreads();

    int tq = tid & 7, grp = tid >> 3;
    int tb = tq * 8, oc2 = grp * 2;

    for (int tile = blockIdx.x; tile < NB * 256; tile += gridDim.x) {
        int b = tile >> 8;
        int t0 = (tile & 255) << 6;
        __syncthreads();
        for (int i = tid; i < 256 * 65; i += 256) {
            int ic = i / 65, jj = i - ic * 65;
            int t = (jj < 64) ? (t0 + jj) : (t0 - 1);
            Xs[ic * 68 + jj] = (t >= 0) ? x[((b * 256 + ic) << 14) + t] : 0.f;
        }
        __syncthreads();

        float acc[2][8];
#pragma unroll
        for (int a = 0; a < 2; a++)
#pragma unroll
            for (int j = 0; j < 8; j++) acc[a][j] = 0.f;

#pragma unroll 2
        for (int ic = 0; ic < 256; ic++) {
            const float* xp = Xs + ic * 68 + tb;
            float4 x0 = *(const float4*)xp;
            float4 x1 = *(const float4*)(xp + 4);
            float xm1 = (tb == 0) ? Xs[ic * 68 + 64] : Xs[ic * 68 + tb - 1];
            float2 w0 = *(const float2*)(Wf_s + ic * 128 + oc2);
            float2 w1 = *(const float2*)(Wf_s + ic * 128 + 64 + oc2);
            float xc[8] = {x0.x, x0.y, x0.z, x0.w, x1.x, x1.y, x1.z, x1.w};
            float xpv[8] = {xm1, xc[0], xc[1], xc[2], xc[3], xc[4], xc[5], xc[6]};
            float wa[2] = {w0.x, w0.y};
            float wb[2] = {w1.x, w1.y};
#pragma unroll
            for (int a = 0; a < 2; a++)
#pragma unroll
                for (int j = 0; j < 8; j++)
                    acc[a][j] += wa[a] * xpv[j] + wb[a] * xc[j];
        }

#pragma unroll
        for (int a = 0; a < 2; a++) {
            int oc = oc2 + a;
            float bv = bs[oc];
            float* hp = &g_h[0][((b * 64 + oc) << 14) + t0 + tb];
            float4 v0, v1;
            v0.x = tanhf(acc[a][0] + bv); v0.y = tanhf(acc[a][1] + bv);
            v0.z = tanhf(acc[a][2] + bv); v0.w = tanhf(acc[a][3] + bv);
            v1.x = tanhf(acc[a][4] + bv); v1.y = tanhf(acc[a][5] + bv);
            v1.z = tanhf(acc[a][6] + bv); v1.w = tanhf(acc[a][7] + bv);
            *(float4*)hp = v0;
            *(float4*)(hp + 4) = v1;
        }
    }
}

// =======================================================================
// Kernel 2 (v6 — HMMA, unchanged from R7 passing version)
// =======================================================================
#define GATE_SMEM 222208
__global__ __launch_bounds__(512) void gate_kernel(
    int layer, int dil, int hsel,
    const float* __restrict__ c,
    const float* __restrict__ W_dil, const float* __restrict__ b_dil,
    const float* __restrict__ W_c, const float* __restrict__ b_c)
{
    extern __shared__ float smf[];
    char* smem = (char*)smf;

    int tid = threadIdx.x;
    int lane = tid & 31, warp = tid >> 5;
    const float* Wd = W_dil + layer * 24576;
    const float* Wc = W_c + layer * 10240;
    const float* h_in = g_h[hsel];

    __nv_bfloat16* Ah_s = (__nv_bfloat16*)(smem + 1024);
    __nv_bfloat16* Al_s = (__nv_bfloat16*)(smem + 72704);
    __nv_bfloat16* Bh_s = (__nv_bfloat16*)(smem + 144384);
    __nv_bfloat16* Bl_s = (__nv_bfloat16*)(smem + 183296);
    float* ys = (float*)(smem + 144384);    // overlay on B region

    if (tid < 128) {   // bias, permuted-gate indexed
        int g = (tid & 1) ? 64 + (tid >> 1) : (tid >> 1);
        smf[tid] = b_dil[layer * 128 + g] + b_c[layer * 128 + g];
    }
    // ---- stage A (weights, hi/lo bf16), once per layer ----
    for (int i = tid; i < 128 * 272; i += 512) {
        int pg = i / 272, k = i - pg * 272;
        int g = (pg & 1) ? 64 + (pg >> 1) : (pg >> 1);
        float w = (k < 192) ? Wd[g * 192 + (k & 63) * 3 + (k >> 6)]
                            : Wc[g * 80 + (k - 192)];
        __nv_bfloat16 wh = __float2bfloat16(w);
        Ah_s[pg * 280 + k] = wh;
        Al_s[pg * 280 + k] = __float2bfloat16(w - __bfloat162float(wh));
    }
    __syncthreads();

    int m0 = (warp & 7) * 16;
    int n0 = (warp >> 3) * 64;
    int r0 = m0 + (lane >> 2);
    int q = (lane & 3) * 2;

    for (int tile = blockIdx.x; tile < NB * 128; tile += gridDim.x) {
        int b = tile >> 7;
        int t0 = (tile & 127) << 7;

        float d[8][4];
#pragma unroll
        for (int nt = 0; nt < 8; nt++)
#pragma unroll
            for (int e = 0; e < 4; e++) d[nt][e] = 0.f;

#pragma unroll 1
        for (int chunk = 0; chunk < 2; chunk++) {
            int ug0 = chunk ? 18 : 0;
            int ug1 = chunk ? 34 : 18;
            for (int u = ug0 * 4 + warp; u < ug1 * 4; u += 16) {
                int kg = u >> 2, nb = u & 3;
                int n = (nb << 5) + lane;
                int t = t0 + n;
                float v[8];
                if (kg < 24) {
                    int tap = kg >> 3, rb = (kg & 7) << 3;
                    int ts = t - (2 - tap) * dil;
                    const float* hp = h_in + ((b * 64 + rb) << 14) + ts;
                    if (ts >= 0) {
#pragma unroll
                        for (int j = 0; j < 8; j++) v[j] = hp[j << 14];
                    } else {
#pragma unroll
                        for (int j = 0; j < 8; j++) v[j] = 0.f;
                    }
                } else {
                    int cb = (kg - 24) << 3;
                    const float* cp = c + ((b * 80 + cb) << 14) + t;
#pragma unroll
                    for (int j = 0; j < 8; j++) v[j] = cp[j << 14];
                }
                uint32_t ph[4], pl[4];
#pragma unroll
                for (int m = 0; m < 4; m++) {
                    float a0 = v[2 * m], a1 = v[2 * m + 1];
                    __nv_bfloat16 h0 = __float2bfloat16(a0);
                    __nv_bfloat16 h1 = __float2bfloat16(a1);
                    ph[m] = pk_bf2(a0, a1);
                    pl[m] = pk_bf2(a0 - __bfloat162float(h0),
                                   a1 - __bfloat162float(h1));
                }
                int klocal = kg * 8 - (chunk ? 144 : 0);
                *(uint4*)(Bh_s + n * 152 + klocal) = make_uint4(ph[0], ph[1], ph[2], ph[3]);
                *(uint4*)(Bl_s + n * 152 + klocal) = make_uint4(pl[0], pl[1], pl[2], pl[3]);
            }
            __syncthreads();

            int nk = chunk ? 8 : 9;
            int kAbase = chunk ? 144 : 0;
#pragma unroll 1
            for (int pass = 0; pass < 3; pass++) {
                const __nv_bfloat16* Ab = (pass == 2) ? Al_s : Ah_s;
                const __nv_bfloat16* Bb = (pass == 1) ? Bl_s : Bh_s;
#pragma unroll 1
                for (int ks = 0; ks < nk; ks++) {
                    int kA = kAbase + ks * 16;
                    int kB = ks * 16;
                    uint32_t a0 = *(const uint32_t*)(Ab + r0 * 280 + kA + q);
                    uint32_t a1 = *(const uint32_t*)(Ab + (r0 + 8) * 280 + kA + q);
                    uint32_t a2 = *(const uint32_t*)(Ab + r0 * 280 + kA + 8 + q);
                    uint32_t a3 = *(const uint32_t*)(Ab + (r0 + 8) * 280 + kA + 8 + q);
#pragma unroll
                    for (int nt = 0; nt < 8; nt++) {
                        int n = n0 + nt * 8 + (lane >> 2);
                        uint32_t b0 = *(const uint32_t*)(Bb + n * 152 + kB + q);
                        uint32_t b1 = *(const uint32_t*)(Bb + n * 152 + kB + 8 + q);
                        mma_bf16(d[nt], a0, a1, a2, a3, b0, b1);
                    }
                }
            }
            __syncthreads();
        }

#pragma unroll
        for (int nt = 0; nt < 8; nt++) {
            int col = n0 + nt * 8 + q;
            *(float2*)(ys + r0 * 132 + col)       = make_float2(d[nt][0], d[nt][1]);
            *(float2*)(ys + (r0 + 8) * 132 + col) = make_float2(d[nt][2], d[nt][3]);
        }
        __syncthreads();

        {
            int i = tid >> 3;
            int qb = tid & 7;
            float ba = smf[2 * i], bb = smf[2 * i + 1];
            const float* ya = ys + (2 * i) * 132 + qb * 16;
            const float* yb = ys + (2 * i + 1) * 132 + qb * 16;
            float* zp = &g_z[((b * 64 + i) << 14) + t0 + qb * 16];
#pragma unroll
            for (int e = 0; e < 4; e++) {
                float4 av = *(const float4*)(ya + e * 4);
                float4 bv = *(const float4*)(yb + e * 4);
                float4 zv;
                zv.x = tanhf(av.x + ba) * sigmoidf_(bv.x + bb);
                zv.y = tanhf(av.y + ba) * sigmoidf_(bv.y + bb);
                zv.z = tanhf(av.z + ba) * sigmoidf_(bv.z + bb);
                zv.w = tanhf(av.w + ba) * sigmoidf_(bv.w + bb);
                *(float4*)(zp + e * 4) = zv;
            }
        }
        __syncthreads();
    }
}

// =======================================================================
// Kernel 3 (v4 — HMMA): combined skip+out GEMM, hi/lo split.
//   D[m][n] = sum_k W[m][k]*z[n][k]; M=320 (256 skip + 64 out), K=64,
//   N=256 time tile. Epilogue straight from mma accumulators.
// SMEM (bytes):
//   0      : bsk 256f (1024) | 1024: bo 64f (256) | pad -> 1536
//   1536   : A_hi bf16[320][88] (56320)
//   57856  : A_lo (56320)
//   114176 : B_hi bf16[256][88] (45056)
//   159232 : B_lo (45056)   total 204288
// stride 88 elem = 176 B = 44 words (44 mod 32 = 12 -> conflict-free quads)
// =======================================================================
#define SKIPOUT_SMEM 204288
__global__ __launch_bounds__(512) void skipout_kernel(
    int layer, int hsel,
    const float* __restrict__ W_skip, const float* __restrict__ b_skip,
    const float* __restrict__ W_out, const float* __restrict__ b_out)
{
    extern __shared__ float smf[];
    char* smem = (char*)smf;

    int tid = threadIdx.x;
    int lane = tid & 31, warp = tid >> 5;
    const float* Wsk = W_skip + layer * 256 * 64;
    const float* Wo  = W_out + layer * 64 * 64;
    const float* h_in = g_h[hsel];
    float* h_out = g_h[1 - hsel];

    float* bsk_s = smf;          // 256
    float* bo_s  = smf + 256;    // 64
    __nv_bfloat16* Ah = (__nv_bfloat16*)(smem + 1536);
    __nv_bfloat16* Al = (__nv_bfloat16*)(smem + 57856);
    __nv_bfloat16* Bh = (__nv_bfloat16*)(smem + 114176);
    __nv_bfloat16* Bl = (__nv_bfloat16*)(smem + 159232);

    if (tid < 256) bsk_s[tid] = b_skip[layer * 256 + tid];
    if (tid < 64)  bo_s[tid]  = b_out[layer * 64 + tid];

    // ---- stage A (320 x 64 weights, hi/lo), once per layer ----
    for (int i = tid; i < 320 * 64; i += 512) {
        int m = i >> 6, k = i & 63;
        float w = (m < 256) ? Wsk[(m << 6) + k] : Wo[((m - 256) << 6) + k];
        __nv_bfloat16 wh = __float2bfloat16(w);
        Ah[m * 88 + k] = wh;
        Al[m * 88 + k] = __float2bfloat16(w - __bfloat162float(wh));
    }
    __syncthreads();

    int q = (lane & 3) * 2;
    int rl = lane >> 2;

    for (int tile = blockIdx.x; tile < NB * 64; tile += gridDim.x) {
        int b = tile >> 6;
        int t0 = (tile & 63) << 8;

        // ---- stage B: z[64][256t] -> Bs[n][k] hi/lo. 64 units ----
        for (int u = warp; u < 64; u += 16) {
            int kg = u >> 3, nb = u & 7;
            int n = (nb << 5) + lane;
            int t = t0 + n;
            const float* zp = g_z + ((b * 64 + kg * 8) << 14) + t;
            float v[8];
#pragma unroll
            for (int j = 0; j < 8; j++) v[j] = zp[j << 14];
            uint32_t ph[4], pl[4];
#pragma unroll
            for (int m = 0; m < 4; m++) {
                float a0 = v[2 * m], a1 = v[2 * m + 1];
                __nv_bfloat16 h0 = __float2bfloat16(a0);
                __nv_bfloat16 h1 = __float2bfloat16(a1);
                ph[m] = pk_bf2(a0, a1);
                pl[m] = pk_bf2(a0 - __bfloat162float(h0),
                               a1 - __bfloat162float(h1));
            }
            *(uint4*)(Bh + n * 88 + kg * 8) = make_uint4(ph[0], ph[1], ph[2], ph[3]);
            *(uint4*)(Bl + n * 88 + kg * 8) = make_uint4(pl[0], pl[1], pl[2], pl[3]);
        }
        __syncthreads();

        // ---- compute + epilogue: 80 units (20 m-tiles x 4 n64-groups) ----
        for (int u = warp; u < 80; u += 16) {
            int mt = u >> 2, ng = u & 3;
            int m0 = mt << 4, n0g = ng << 6;
            int r0 = m0 + rl;

            float d[8][4];
#pragma unroll
            for (int nt = 0; nt < 8; nt++)
#pragma unroll
                for (int e = 0; e < 4; e++) d[nt][e] = 0.f;

#pragma unroll 1
            for (int pass = 0; pass < 3; pass++) {
                const __nv_bfloat16* Ab = (pass == 2) ? Al : Ah;
                const __nv_bfloat16* Bb = (pass == 1) ? Bl : Bh;
#pragma unroll
                for (int ks = 0; ks < 4; ks++) {
                    int kA = ks * 16;
                    uint32_t a0 = *(const uint32_t*)(Ab + r0 * 88 + kA + q);
                    uint32_t a1 = *(const uint32_t*)(Ab + (r0 + 8) * 88 + kA + q);
                    uint32_t a2 = *(const uint32_t*)(Ab + r0 * 88 + kA + 8 + q);
                    uint32_t a3 = *(const uint32_t*)(Ab + (r0 + 8) * 88 + kA + 8 + q);
#pragma unroll
                    for (int nt = 0; nt < 8; nt++) {
                        int n = n0g + nt * 8 + rl;
                        uint32_t b0 = *(const uint32_t*)(Bb + n * 88 + kA + q);
                        uint32_t b1 = *(const uint32_t*)(Bb + n * 88 + kA + 8 + q);
                        mma_bf16(d[nt], a0, a1, a2, a3, b0, b1);
                    }
                }
            }

            // ---- epilogue from registers ----
            if (m0 < 256) {
#pragma unroll
                for (int hh = 0; hh < 2; hh++) {
                    int sc = r0 + hh * 8;
                    float bsv = bsk_s[sc];
                    float* sp = &g_skip[((b * 256 + sc) << 14) + t0 + n0g + q];
                    if (layer == 0) {
#pragma unroll
                        for (int nt = 0; nt < 8; nt++) {
                            *(float2*)(sp + nt * 8) =
                                make_float2(d[nt][hh * 2] + bsv, d[nt][hh * 2 + 1] + bsv);
                        }
                    } else {
#pragma unroll
                        for (int nt = 0; nt < 8; nt++) {
                            float2 o = *(float2*)(sp + nt * 8);
                            *(float2*)(sp + nt * 8) = make_float2(
                                (o.x + d[nt][hh * 2] + bsv) * SQRT_HALF_F,
                                (o.y + d[nt][hh * 2 + 1] + bsv) * SQRT_HALF_F);
                        }
                    }
                }
            } else {
#pragma unroll
                for (int hh = 0; hh < 2; hh++) {
                    int oc = r0 - 256 + hh * 8;
                    float bov = bo_s[oc];
                    const float* hip = h_in + ((b * 64 + oc) << 14) + t0 + n0g + q;
                    float* hop = h_out + ((b * 64 + oc) << 14) + t0 + n0g + q;
#pragma unroll
                    for (int nt = 0; nt < 8; nt++) {
                        float2 hv = *(const float2*)(hip + nt * 8);
                        *(float2*)(hop + nt * 8) = make_float2(
                            (d[nt][hh * 2] + bov + hv.x) * SQRT_HALF_F,
                            (d[nt][hh * 2 + 1] + bov + hv.y) * SQRT_HALF_F);
                    }
                }
            }
        }
        __syncthreads();   // all B reads done before next tile restages
    }
}

// =======================================================================
// Kernel 4 (v3): dense 256x256, W staged in 32-row chunks, 2 CTAs/SM.
// =======================================================================
#define DENSE_SMEM 99840
__global__ __launch_bounds__(512, 2) void dense256_kernel(
    int stage, float* __restrict__ final_out,
    const float* __restrict__ W, const float* __restrict__ bias)
{
    extern __shared__ float sm[];
    float* Ss = sm;
    float* Wt = Ss + 16384;
    float* bb = Wt + 8320;

    const float* in = (stage == 0) ? g_skip : g_tmp;
    float* out = (stage == 0) ? g_tmp : final_out;

    int tid = threadIdx.x;
    if (tid < 256) bb[tid] = bias[tid];

    int tq = tid & 7, ocg = tid >> 3;
    int tb = tq * 8, oc4 = ocg * 4;

    for (int tile = blockIdx.x; tile < NB * 256; tile += gridDim.x) {
        int b = tile >> 8;
        int t0 = (tile & 255) << 6;

        __syncthreads();
        for (int i = tid; i < 16384; i += 512) {
            int sc = i >> 6, j = i & 63;
            float v = in[((b * 256 + sc) << 14) + t0 + j];
            if (stage == 0) v = fmaxf(v, 0.f);
            Ss[i] = v;
        }

        ull acc[4][4];
#pragma unroll
        for (int a = 0; a < 4; a++)
#pragma unroll
            for (int p = 0; p < 4; p++) acc[a][p] = 0ull;

        for (int c0 = 0; c0 < 256; c0 += 32) {
            __syncthreads();
            for (int i = tid; i < 32 * 256; i += 512) {
                int scc = i & 31, oc = i >> 5;
                Wt[scc * 260 + oc] = W[oc * 256 + c0 + scc];
            }
            __syncthreads();
#pragma unroll 4
            for (int scc = 0; scc < 32; scc++) {
                const float* sp = Ss + (c0 + scc) * 64 + tb;
                ulonglong2 zA = *(const ulonglong2*)sp;
                ulonglong2 zB = *(const ulonglong2*)(sp + 4);
                float4 w = *(const float4*)(Wt + scc * 260 + oc4);
                ull w0 = pack2(w.x), w1 = pack2(w.y), w2 = pack2(w.z), w3 = pack2(w.w);
                fma2(acc[0][0], w0, zA.x); fma2(acc[1][0], w1, zA.x);
                fma2(acc[2][0], w2, zA.x); fma2(acc[3][0], w3, zA.x);
                fma2(acc[0][1], w0, zA.y); fma2(acc[1][1], w1, zA.y);
                fma2(acc[2][1], w2, zA.y); fma2(acc[3][1], w3, zA.y);
                fma2(acc[0][2], w0, zB.x); fma2(acc[1][2], w1, zB.x);
                fma2(acc[2][2], w2, zB.x); fma2(acc[3][2], w3, zB.x);
                fma2(acc[0][3], w0, zB.y); fma2(acc[1][3], w1, zB.y);
                fma2(acc[2][3], w2, zB.y); fma2(acc[3][3], w3, zB.y);
            }
        }

#pragma unroll
        for (int a = 0; a < 4; a++) {
            int oc = oc4 + a;
            float bv = bb[oc];
            float2 q0 = unpack2(acc[a][0]);
            float2 q1 = unpack2(acc[a][1]);
            float2 q2 = unpack2(acc[a][2]);
            float2 q3 = unpack2(acc[a][3]);
            float* op = out + ((b * 256 + oc) << 14) + t0 + tb;
            float4 v0 = make_float4(q0.x + bv, q0.y + bv, q1.x + bv, q1.y + bv);
            float4 v1 = make_float4(q2.x + bv, q2.y + bv, q3.x + bv, q3.y + bv);
            if (stage == 0) {
                v0.x = fmaxf(v0.x, 0.f); v0.y = fmaxf(v0.y, 0.f);
                v0.z = fmaxf(v0.z, 0.f); v0.w = fmaxf(v0.w, 0.f);
                v1.x = fmaxf(v1.x, 0.f); v1.y = fmaxf(v1.y, 0.f);
                v1.z = fmaxf(v1.z, 0.f); v1.w = fmaxf(v1.w, 0.f);
            }
            *(float4*)op = v0;
            *(float4*)(op + 4) = v1;
        }
    }
}

// =======================================================================
extern "C" void kernel_launch(void* const* d_in, const int* in_sizes, int n_in,
                              void* d_out, int out_size)
{
    const float* x       = (const float*)d_in[0];
    const float* c       = (const float*)d_in[1];
    const float* W_first = (const float*)d_in[2];
    const float* b_first = (const float*)d_in[3];
    const float* W_dil   = (const float*)d_in[4];
    const float* b_dil   = (const float*)d_in[5];
    const float* W_c     = (const float*)d_in[6];
    const float* b_c     = (const float*)d_in[7];
    const float* W_skip  = (const float*)d_in[8];
    const float* b_skip  = (const float*)d_in[9];
    const float* W_out   = (const float*)d_in[10];
    const float* b_out   = (const float*)d_in[11];
    const float* W_last1 = (const float*)d_in[12];
    const float* b_last1 = (const float*)d_in[13];
    const float* W_last2 = (const float*)d_in[14];
    const float* b_last2 = (const float*)d_in[15];
    float* out = (float*)d_out;

    cudaFuncSetAttribute(first_kernel,  cudaFuncAttributeMaxDynamicSharedMemorySize, FIRST_SMEM);
    cudaFuncSetAttribute(gate_kernel,   cudaFuncAttributeMaxDynamicSharedMemorySize, GATE_SMEM);
    cudaFuncSetAttribute(skipout_kernel,cudaFuncAttributeMaxDynamicSharedMemorySize, SKIPOUT_SMEM);
    cudaFuncSetAttribute(dense256_kernel,cudaFuncAttributeMaxDynamicSharedMemorySize, DENSE_SMEM);

    int dev = 0;
    cudaGetDevice(&dev);
    int sm_count = 148;
    cudaDeviceGetAttribute(&sm_count, cudaDevAttrMultiProcessorCount, dev);
    int grid1 = sm_count;
    int grid2 = 2 * sm_count;

    first_kernel<<<grid1, 256, FIRST_SMEM>>>(x, W_first, b_first);

    for (int l = 0; l < 20; l++) {
        int dil = 1 << (l % 10);
        int hsel = l & 1;   // layer l reads g_h[hsel], writes g_h[1-hsel]
        gate_kernel<<<grid1, 512, GATE_SMEM>>>(l, dil, hsel, c,
                                               W_dil, b_dil, W_c, b_c);
        skipout_kernel<<<grid1, 512, SKIPOUT_SMEM>>>(l, hsel,
                                                     W_skip, b_skip, W_out, b_out);
    }

    dense256_kernel<<<grid2, 512, DENSE_SMEM>>>(0, out, W_last1, b_last1);
    dense256_kernel<<<grid2, 512, DENSE_SMEM>>>(1, out, W_last2, b_last2);
}

// round 9
// speedup vs baseline: 1.7291x; 1.1252x over previous
#include <cuda_runtime.h>
#include <cuda_bf16.h>
#include <stdint.h>
#include <math.h>

#define T_LEN 16384
#define NB 4

static __device__ __forceinline__ float sigmoidf_(float v) {
    return 1.0f / (1.0f + __expf(-v));
}

#define SQRT_HALF_F 0.70710678118654752f

typedef unsigned long long ull;

// packed f32x2 helpers (dense kernel)
static __device__ __forceinline__ ull pack2(float v) {
    ull r;
    asm("mov.b64 %0, {%1, %1};" : "=l"(r) : "f"(v));
    return r;
}
static __device__ __forceinline__ void fma2(ull& d, ull a, ull b) {
    asm("fma.rn.f32x2 %0, %1, %2, %0;" : "+l"(d) : "l"(a), "l"(b));
}
static __device__ __forceinline__ float2 unpack2(ull v) {
    float2 r;
    asm("mov.b64 {%0, %1}, %2;" : "=f"(r.x), "=f"(r.y) : "l"(v));
    return r;
}

// bf16 HMMA m16n8k16 (base-target PTX)
static __device__ __forceinline__ void mma_bf16(
    float* d, uint32_t a0, uint32_t a1, uint32_t a2, uint32_t a3,
    uint32_t b0, uint32_t b1)
{
    asm volatile(
        "mma.sync.aligned.m16n8k16.row.col.f32.bf16.bf16.f32 "
        "{%0,%1,%2,%3}, {%4,%5,%6,%7}, {%8,%9}, {%0,%1,%2,%3};"
        : "+f"(d[0]), "+f"(d[1]), "+f"(d[2]), "+f"(d[3])
        : "r"(a0), "r"(a1), "r"(a2), "r"(a3), "r"(b0), "r"(b1));
}
// ldmatrix x4 (base PTX sm_75+)
static __device__ __forceinline__ void ldsm_x4(uint32_t* r, uint32_t addr) {
    asm volatile(
        "ldmatrix.sync.aligned.m8n8.x4.shared.b16 {%0,%1,%2,%3}, [%4];"
        : "=r"(r[0]), "=r"(r[1]), "=r"(r[2]), "=r"(r[3]) : "r"(addr));
}
static __device__ __forceinline__ uint32_t pk_bf2(float a, float b) {
    __nv_bfloat162 t;
    t.x = __float2bfloat16(a);
    t.y = __float2bfloat16(b);
    return *(uint32_t*)&t;
}
static __device__ __forceinline__ uint32_t smem_u32(const void* p) {
    uint32_t a;
    asm("{ .reg .u64 t; cvta.to.shared.u64 t, %1; cvt.u32.u64 %0, t; }"
        : "=r"(a) : "l"(p));
    return a;
}

// ---------------- scratch (allocation-free: __device__ globals) ----------------
__device__ float g_h[2][NB * 64 * T_LEN];     // residual ping-pong
__device__ float g_z[NB * 64 * T_LEN];        // gated activations per layer
__device__ float g_skip[NB * 256 * T_LEN];    // skip accumulator
__device__ float g_tmp[NB * 256 * T_LEN];     // final intermediate

// =======================================================================
// Kernel 1: first conv (k=2 causal, 256 -> 64) + tanh. (unchanged)
// =======================================================================
#define FIRST_SMEM 200960
__global__ __launch_bounds__(256) void first_kernel(
    const float* __restrict__ x, const float* __restrict__ Wf,
    const float* __restrict__ bf)
{
    extern __shared__ float sm[];
    float* Wf_s = sm;
    float* bs   = Wf_s + 32768;
    float* Xs   = bs + 64;

    int tid = threadIdx.x;
    for (int i = tid; i < 64 * 256 * 2; i += 256) {
        int oc = i >> 9; int ic = (i >> 1) & 255; int k = i & 1;
        Wf_s[ic * 128 + k * 64 + oc] = Wf[i];
    }
    if (tid < 64) bs[tid] = bf[tid];
    __syncthreads();

    int tq = tid & 7, grp = tid >> 3;
    int tb = tq * 8, oc2 = grp * 2;

    for (int tile = blockIdx.x; tile < NB * 256; tile += gridDim.x) {
        int b = tile >> 8;
        int t0 = (tile & 255) << 6;
        __syncthreads();
        for (int i = tid; i < 256 * 65; i += 256) {
            int ic = i / 65, jj = i - ic * 65;
            int t = (jj < 64) ? (t0 + jj) : (t0 - 1);
            Xs[ic * 68 + jj] = (t >= 0) ? x[((b * 256 + ic) << 14) + t] : 0.f;
        }
        __syncthreads();

        float acc[2][8];
#pragma unroll
        for (int a = 0; a < 2; a++)
#pragma unroll
            for (int j = 0; j < 8; j++) acc[a][j] = 0.f;

#pragma unroll 2
        for (int ic = 0; ic < 256; ic++) {
            const float* xp = Xs + ic * 68 + tb;
            float4 x0 = *(const float4*)xp;
            float4 x1 = *(const float4*)(xp + 4);
            float xm1 = (tb == 0) ? Xs[ic * 68 + 64] : Xs[ic * 68 + tb - 1];
            float2 w0 = *(const float2*)(Wf_s + ic * 128 + oc2);
            float2 w1 = *(const float2*)(Wf_s + ic * 128 + 64 + oc2);
            float xc[8] = {x0.x, x0.y, x0.z, x0.w, x1.x, x1.y, x1.z, x1.w};
            float xpv[8] = {xm1, xc[0], xc[1], xc[2], xc[3], xc[4], xc[5], xc[6]};
            float wa[2] = {w0.x, w0.y};
            float wb[2] = {w1.x, w1.y};
#pragma unroll
            for (int a = 0; a < 2; a++)
#pragma unroll
                for (int j = 0; j < 8; j++)
                    acc[a][j] += wa[a] * xpv[j] + wb[a] * xc[j];
        }

#pragma unroll
        for (int a = 0; a < 2; a++) {
            int oc = oc2 + a;
            float bv = bs[oc];
            float* hp = &g_h[0][((b * 64 + oc) << 14) + t0 + tb];
            float4 v0, v1;
            v0.x = tanhf(acc[a][0] + bv); v0.y = tanhf(acc[a][1] + bv);
            v0.z = tanhf(acc[a][2] + bv); v0.w = tanhf(acc[a][3] + bv);
            v1.x = tanhf(acc[a][4] + bv); v1.y = tanhf(acc[a][5] + bv);
            v1.z = tanhf(acc[a][6] + bv); v1.w = tanhf(acc[a][7] + bv);
            *(float4*)hp = v0;
            *(float4*)(hp + 4) = v1;
        }
    }
}

// =======================================================================
// Kernel 2 (v7 — HMMA + ldmatrix, fused hi/lo): gate.
// Layout identical to R8; mainloop now 10 LDSM + 24 mma per k-step.
// =======================================================================
#define GATE_SMEM 222208
__global__ __launch_bounds__(512) void gate_kernel(
    int layer, int dil, int hsel,
    const float* __restrict__ c,
    const float* __restrict__ W_dil, const float* __restrict__ b_dil,
    const float* __restrict__ W_c, const float* __restrict__ b_c)
{
    extern __shared__ float smf[];
    char* smem = (char*)smf;

    int tid = threadIdx.x;
    int lane = tid & 31, warp = tid >> 5;
    const float* Wd = W_dil + layer * 24576;
    const float* Wc = W_c + layer * 10240;
    const float* h_in = g_h[hsel];

    __nv_bfloat16* Ah_s = (__nv_bfloat16*)(smem + 1024);
    __nv_bfloat16* Al_s = (__nv_bfloat16*)(smem + 72704);
    __nv_bfloat16* Bh_s = (__nv_bfloat16*)(smem + 144384);
    __nv_bfloat16* Bl_s = (__nv_bfloat16*)(smem + 183296);
    float* ys = (float*)(smem + 144384);    // overlay on B region

    if (tid < 128) {   // bias, permuted-gate indexed
        int g = (tid & 1) ? 64 + (tid >> 1) : (tid >> 1);
        smf[tid] = b_dil[layer * 128 + g] + b_c[layer * 128 + g];
    }
    // ---- stage A (weights, hi/lo bf16), once per layer ----
    for (int i = tid; i < 128 * 272; i += 512) {
        int pg = i / 272, k = i - pg * 272;
        int g = (pg & 1) ? 64 + (pg >> 1) : (pg >> 1);
        float w = (k < 192) ? Wd[g * 192 + (k & 63) * 3 + (k >> 6)]
                            : Wc[g * 80 + (k - 192)];
        __nv_bfloat16 wh = __float2bfloat16(w);
        Ah_s[pg * 280 + k] = wh;
        Al_s[pg * 280 + k] = __float2bfloat16(w - __bfloat162float(wh));
    }
    __syncthreads();

    int m0 = (warp & 7) * 16;
    int n0 = (warp >> 3) * 64;
    int r0 = m0 + (lane >> 2);      // accumulator-layout row (epilogue)
    int q = (lane & 3) * 2;

    // ---- ldmatrix lane base addresses ----
    uint32_t sb = smem_u32(smem);
    uint32_t aBase = sb + 1024 +
        (uint32_t)(((m0 + (lane & 15)) * 280 + (lane >> 4) * 8) * 2);
    const uint32_t A_LO = 71680;
    uint32_t bBase[4];
#pragma unroll
    for (int p = 0; p < 4; p++) {
        int n = n0 + ((lane >> 4) & 1) * 8 + (lane & 7) + 16 * p;
        bBase[p] = sb + 144384 + (uint32_t)((n * 152) * 2 + (lane & 8) * 2);
    }
    const uint32_t B_LO = 38912;

    for (int tile = blockIdx.x; tile < NB * 128; tile += gridDim.x) {
        int b = tile >> 7;
        int t0 = (tile & 127) << 7;

        float d[8][4];
#pragma unroll
        for (int nt = 0; nt < 8; nt++)
#pragma unroll
            for (int e = 0; e < 4; e++) d[nt][e] = 0.f;

#pragma unroll 1
        for (int chunk = 0; chunk < 2; chunk++) {
            int ug0 = chunk ? 18 : 0;
            int ug1 = chunk ? 34 : 18;
            for (int u = ug0 * 4 + warp; u < ug1 * 4; u += 16) {
                int kg = u >> 2, nb = u & 3;
                int n = (nb << 5) + lane;
                int t = t0 + n;
                float v[8];
                if (kg < 24) {
                    int tap = kg >> 3, rb = (kg & 7) << 3;
                    int ts = t - (2 - tap) * dil;
                    const float* hp = h_in + ((b * 64 + rb) << 14) + ts;
                    if (ts >= 0) {
#pragma unroll
                        for (int j = 0; j < 8; j++) v[j] = hp[j << 14];
                    } else {
#pragma unroll
                        for (int j = 0; j < 8; j++) v[j] = 0.f;
                    }
                } else {
                    int cb = (kg - 24) << 3;
                    const float* cp = c + ((b * 80 + cb) << 14) + t;
#pragma unroll
                    for (int j = 0; j < 8; j++) v[j] = cp[j << 14];
                }
                uint32_t ph[4], pl[4];
#pragma unroll
                for (int m = 0; m < 4; m++) {
                    float a0 = v[2 * m], a1 = v[2 * m + 1];
                    __nv_bfloat16 h0 = __float2bfloat16(a0);
                    __nv_bfloat16 h1 = __float2bfloat16(a1);
                    ph[m] = pk_bf2(a0, a1);
                    pl[m] = pk_bf2(a0 - __bfloat162float(h0),
                                   a1 - __bfloat162float(h1));
                }
                int klocal = kg * 8 - (chunk ? 144 : 0);
                *(uint4*)(Bh_s + n * 152 + klocal) = make_uint4(ph[0], ph[1], ph[2], ph[3]);
                *(uint4*)(Bl_s + n * 152 + klocal) = make_uint4(pl[0], pl[1], pl[2], pl[3]);
            }
            __syncthreads();

            int nk = chunk ? 8 : 9;
            int kAbase = chunk ? 144 : 0;
#pragma unroll 1
            for (int ks = 0; ks < nk; ks++) {
                uint32_t offA = (uint32_t)((kAbase + ks * 16) * 2);
                uint32_t offB = (uint32_t)(ks * 16 * 2);
                uint32_t ah[4], al[4];
                ldsm_x4(ah, aBase + offA);
                ldsm_x4(al, aBase + A_LO + offA);
#pragma unroll
                for (int p = 0; p < 4; p++) {
                    uint32_t bh[4], bl[4];
                    ldsm_x4(bh, bBase[p] + offB);
                    ldsm_x4(bl, bBase[p] + B_LO + offB);
                    int e0 = 2 * p, e1 = 2 * p + 1;
                    mma_bf16(d[e0], ah[0], ah[1], ah[2], ah[3], bh[0], bh[1]);
                    mma_bf16(d[e0], ah[0], ah[1], ah[2], ah[3], bl[0], bl[1]);
                    mma_bf16(d[e0], al[0], al[1], al[2], al[3], bh[0], bh[1]);
                    mma_bf16(d[e1], ah[0], ah[1], ah[2], ah[3], bh[2], bh[3]);
                    mma_bf16(d[e1], ah[0], ah[1], ah[2], ah[3], bl[2], bl[3]);
                    mma_bf16(d[e1], al[0], al[1], al[2], al[3], bh[2], bh[3]);
                }
            }
            __syncthreads();
        }

#pragma unroll
        for (int nt = 0; nt < 8; nt++) {
            int col = n0 + nt * 8 + q;
            *(float2*)(ys + r0 * 132 + col)       = make_float2(d[nt][0], d[nt][1]);
            *(float2*)(ys + (r0 + 8) * 132 + col) = make_float2(d[nt][2], d[nt][3]);
        }
        __syncthreads();

        {
            int i = tid >> 3;
            int qb = tid & 7;
            float ba = smf[2 * i], bb = smf[2 * i + 1];
            const float* ya = ys + (2 * i) * 132 + qb * 16;
            const float* yb = ys + (2 * i + 1) * 132 + qb * 16;
            float* zp = &g_z[((b * 64 + i) << 14) + t0 + qb * 16];
#pragma unroll
            for (int e = 0; e < 4; e++) {
                float4 av = *(const float4*)(ya + e * 4);
                float4 bv = *(const float4*)(yb + e * 4);
                float4 zv;
                zv.x = tanhf(av.x + ba) * sigmoidf_(bv.x + bb);
                zv.y = tanhf(av.y + ba) * sigmoidf_(bv.y + bb);
                zv.z = tanhf(av.z + ba) * sigmoidf_(bv.z + bb);
                zv.w = tanhf(av.w + ba) * sigmoidf_(bv.w + bb);
                *(float4*)(zp + e * 4) = zv;
            }
        }
        __syncthreads();
    }
}

// =======================================================================
// Kernel 3 (v5 — HMMA + ldmatrix, fused hi/lo): skip+out.
// =======================================================================
#define SKIPOUT_SMEM 204288
__global__ __launch_bounds__(512) void skipout_kernel(
    int layer, int hsel,
    const float* __restrict__ W_skip, const float* __restrict__ b_skip,
    const float* __restrict__ W_out, const float* __restrict__ b_out)
{
    extern __shared__ float smf[];
    char* smem = (char*)smf;

    int tid = threadIdx.x;
    int lane = tid & 31, warp = tid >> 5;
    const float* Wsk = W_skip + layer * 256 * 64;
    const float* Wo  = W_out + layer * 64 * 64;
    const float* h_in = g_h[hsel];
    float* h_out = g_h[1 - hsel];

    float* bsk_s = smf;          // 256
    float* bo_s  = smf + 256;    // 64
    __nv_bfloat16* Ah = (__nv_bfloat16*)(smem + 1536);
    __nv_bfloat16* Al = (__nv_bfloat16*)(smem + 57856);
    __nv_bfloat16* Bh = (__nv_bfloat16*)(smem + 114176);
    __nv_bfloat16* Bl = (__nv_bfloat16*)(smem + 159232);
    const uint32_t A_LO = 56320, B_LO = 45056;

    if (tid < 256) bsk_s[tid] = b_skip[layer * 256 + tid];
    if (tid < 64)  bo_s[tid]  = b_out[layer * 64 + tid];

    for (int i = tid; i < 320 * 64; i += 512) {
        int m = i >> 6, k = i & 63;
        float w = (m < 256) ? Wsk[(m << 6) + k] : Wo[((m - 256) << 6) + k];
        __nv_bfloat16 wh = __float2bfloat16(w);
        Ah[m * 88 + k] = wh;
        Al[m * 88 + k] = __float2bfloat16(w - __bfloat162float(wh));
    }
    __syncthreads();

    int q = (lane & 3) * 2;
    int rl = lane >> 2;
    uint32_t sb = smem_u32(smem);
    // lane-invariant pieces of ldmatrix addresses
    uint32_t aLaneOff = (uint32_t)(((lane & 15) * 88 + (lane >> 4) * 8) * 2);
    uint32_t bLaneOff = (uint32_t)(((((lane >> 4) & 1) * 8 + (lane & 7)) * 88) * 2
                                   + (lane & 8) * 2);

    for (int tile = blockIdx.x; tile < NB * 64; tile += gridDim.x) {
        int b = tile >> 6;
        int t0 = (tile & 63) << 8;

        // ---- stage B: z[64][256t] -> Bs[n][k] hi/lo ----
        for (int u = warp; u < 64; u += 16) {
            int kg = u >> 3, nb = u & 7;
            int n = (nb << 5) + lane;
            int t = t0 + n;
            const float* zp = g_z + ((b * 64 + kg * 8) << 14) + t;
            float v[8];
#pragma unroll
            for (int j = 0; j < 8; j++) v[j] = zp[j << 14];
            uint32_t ph[4], pl[4];
#pragma unroll
            for (int m = 0; m < 4; m++) {
                float a0 = v[2 * m], a1 = v[2 * m + 1];
                __nv_bfloat16 h0 = __float2bfloat16(a0);
                __nv_bfloat16 h1 = __float2bfloat16(a1);
                ph[m] = pk_bf2(a0, a1);
                pl[m] = pk_bf2(a0 - __bfloat162float(h0),
                               a1 - __bfloat162float(h1));
            }
            *(uint4*)(Bh + n * 88 + kg * 8) = make_uint4(ph[0], ph[1], ph[2], ph[3]);
            *(uint4*)(Bl + n * 88 + kg * 8) = make_uint4(pl[0], pl[1], pl[2], pl[3]);
        }
        __syncthreads();

        // ---- compute + epilogue: 80 units (20 m-tiles x 4 n64-groups) ----
        for (int u = warp; u < 80; u += 16) {
            int mt = u >> 2, ng = u & 3;
            int m0 = mt << 4, n0g = ng << 6;
            int r0 = m0 + rl;

            uint32_t aBase = sb + 1536 + (uint32_t)(m0 * 88 * 2) + aLaneOff;
            uint32_t bBase = sb + 114176 + (uint32_t)(n0g * 88 * 2) + bLaneOff;

            float d[8][4];
#pragma unroll
            for (int nt = 0; nt < 8; nt++)
#pragma unroll
                for (int e = 0; e < 4; e++) d[nt][e] = 0.f;

#pragma unroll
            for (int ks = 0; ks < 4; ks++) {
                uint32_t off = (uint32_t)(ks * 16 * 2);
                uint32_t ah[4], al[4];
                ldsm_x4(ah, aBase + off);
                ldsm_x4(al, aBase + A_LO + off);
#pragma unroll
                for (int p = 0; p < 4; p++) {
                    uint32_t bh[4], bl[4];
                    uint32_t bp = bBase + (uint32_t)(16 * p * 88 * 2) + off;
                    ldsm_x4(bh, bp);
                    ldsm_x4(bl, bp + B_LO);
                    int e0 = 2 * p, e1 = 2 * p + 1;
                    mma_bf16(d[e0], ah[0], ah[1], ah[2], ah[3], bh[0], bh[1]);
                    mma_bf16(d[e0], ah[0], ah[1], ah[2], ah[3], bl[0], bl[1]);
                    mma_bf16(d[e0], al[0], al[1], al[2], al[3], bh[0], bh[1]);
                    mma_bf16(d[e1], ah[0], ah[1], ah[2], ah[3], bh[2], bh[3]);
                    mma_bf16(d[e1], ah[0], ah[1], ah[2], ah[3], bl[2], bl[3]);
                    mma_bf16(d[e1], al[0], al[1], al[2], al[3], bh[2], bh[3]);
                }
            }

            // ---- epilogue from registers ----
            if (m0 < 256) {
#pragma unroll
                for (int hh = 0; hh < 2; hh++) {
                    int sc = r0 + hh * 8;
                    float bsv = bsk_s[sc];
                    float* sp = &g_skip[((b * 256 + sc) << 14) + t0 + n0g + q];
                    if (layer == 0) {
#pragma unroll
                        for (int nt = 0; nt < 8; nt++) {
                            *(float2*)(sp + nt * 8) =
                                make_float2(d[nt][hh * 2] + bsv, d[nt][hh * 2 + 1] + bsv);
                        }
                    } else {
#pragma unroll
                        for (int nt = 0; nt < 8; nt++) {
                            float2 o = *(float2*)(sp + nt * 8);
                            *(float2*)(sp + nt * 8) = make_float2(
                                (o.x + d[nt][hh * 2] + bsv) * SQRT_HALF_F,
                                (o.y + d[nt][hh * 2 + 1] + bsv) * SQRT_HALF_F);
                        }
                    }
                }
            } else {
#pragma unroll
                for (int hh = 0; hh < 2; hh++) {
                    int oc = r0 - 256 + hh * 8;
                    float bov = bo_s[oc];
                    const float* hip = h_in + ((b * 64 + oc) << 14) + t0 + n0g + q;
                    float* hop = h_out + ((b * 64 + oc) << 14) + t0 + n0g + q;
#pragma unroll
                    for (int nt = 0; nt < 8; nt++) {
                        float2 hv = *(const float2*)(hip + nt * 8);
                        *(float2*)(hop + nt * 8) = make_float2(
                            (d[nt][hh * 2] + bov + hv.x) * SQRT_HALF_F,
                            (d[nt][hh * 2 + 1] + bov + hv.y) * SQRT_HALF_F);
                    }
                }
            }
        }
        __syncthreads();
    }
}

// =======================================================================
// Kernel 4 (v3): dense 256x256, FFMA2, 2 CTAs/SM. (unchanged)
// =======================================================================
#define DENSE_SMEM 99840
__global__ __launch_bounds__(512, 2) void dense256_kernel(
    int stage, float* __restrict__ final_out,
    const float* __restrict__ W, const float* __restrict__ bias)
{
    extern __shared__ float sm[];
    float* Ss = sm;
    float* Wt = Ss + 16384;
    float* bb = Wt + 8320;

    const float* in = (stage == 0) ? g_skip : g_tmp;
    float* out = (stage == 0) ? g_tmp : final_out;

    int tid = threadIdx.x;
    if (tid < 256) bb[tid] = bias[tid];

    int tq = tid & 7, ocg = tid >> 3;
    int tb = tq * 8, oc4 = ocg * 4;

    for (int tile = blockIdx.x; tile < NB * 256; tile += gridDim.x) {
        int b = tile >> 8;
        int t0 = (tile & 255) << 6;

        __syncthreads();
        for (int i = tid; i < 16384; i += 512) {
            int sc = i >> 6, j = i & 63;
            float v = in[((b * 256 + sc) << 14) + t0 + j];
            if (stage == 0) v = fmaxf(v, 0.f);
            Ss[i] = v;
        }

        ull acc[4][4];
#pragma unroll
        for (int a = 0; a < 4; a++)
#pragma unroll
            for (int p = 0; p < 4; p++) acc[a][p] = 0ull;

        for (int c0 = 0; c0 < 256; c0 += 32) {
            __syncthreads();
            for (int i = tid; i < 32 * 256; i += 512) {
                int scc = i & 31, oc = i >> 5;
                Wt[scc * 260 + oc] = W[oc * 256 + c0 + scc];
            }
            __syncthreads();
#pragma unroll 4
            for (int scc = 0; scc < 32; scc++) {
                const float* sp = Ss + (c0 + scc) * 64 + tb;
                ulonglong2 zA = *(const ulonglong2*)sp;
                ulonglong2 zB = *(const ulonglong2*)(sp + 4);
                float4 w = *(const float4*)(Wt + scc * 260 + oc4);
                ull w0 = pack2(w.x), w1 = pack2(w.y), w2 = pack2(w.z), w3 = pack2(w.w);
                fma2(acc[0][0], w0, zA.x); fma2(acc[1][0], w1, zA.x);
                fma2(acc[2][0], w2, zA.x); fma2(acc[3][0], w3, zA.x);
                fma2(acc[0][1], w0, zA.y); fma2(acc[1][1], w1, zA.y);
                fma2(acc[2][1], w2, zA.y); fma2(acc[3][1], w3, zA.y);
                fma2(acc[0][2], w0, zB.x); fma2(acc[1][2], w1, zB.x);
                fma2(acc[2][2], w2, zB.x); fma2(acc[3][2], w3, zB.x);
                fma2(acc[0][3], w0, zB.y); fma2(acc[1][3], w1, zB.y);
                fma2(acc[2][3], w2, zB.y); fma2(acc[3][3], w3, zB.y);
            }
        }

#pragma unroll
        for (int a = 0; a < 4; a++) {
            int oc = oc4 + a;
            float bv = bb[oc];
            float2 q0 = unpack2(acc[a][0]);
            float2 q1 = unpack2(acc[a][1]);
            float2 q2 = unpack2(acc[a][2]);
            float2 q3 = unpack2(acc[a][3]);
            float* op = out + ((b * 256 + oc) << 14) + t0 + tb;
            float4 v0 = make_float4(q0.x + bv, q0.y + bv, q1.x + bv, q1.y + bv);
            float4 v1 = make_float4(q2.x + bv, q2.y + bv, q3.x + bv, q3.y + bv);
            if (stage == 0) {
                v0.x = fmaxf(v0.x, 0.f); v0.y = fmaxf(v0.y, 0.f);
                v0.z = fmaxf(v0.z, 0.f); v0.w = fmaxf(v0.w, 0.f);
                v1.x = fmaxf(v1.x, 0.f); v1.y = fmaxf(v1.y, 0.f);
                v1.z = fmaxf(v1.z, 0.f); v1.w = fmaxf(v1.w, 0.f);
            }
            *(float4*)op = v0;
            *(float4*)(op + 4) = v1;
        }
    }
}

// =======================================================================
extern "C" void kernel_launch(void* const* d_in, const int* in_sizes, int n_in,
                              void* d_out, int out_size)
{
    const float* x       = (const float*)d_in[0];
    const float* c       = (const float*)d_in[1];
    const float* W_first = (const float*)d_in[2];
    const float* b_first = (const float*)d_in[3];
    const float* W_dil   = (const float*)d_in[4];
    const float* b_dil   = (const float*)d_in[5];
    const float* W_c     = (const float*)d_in[6];
    const float* b_c     = (const float*)d_in[7];
    const float* W_skip  = (const float*)d_in[8];
    const float* b_skip  = (const float*)d_in[9];
    const float* W_out   = (const float*)d_in[10];
    const float* b_out   = (const float*)d_in[11];
    const float* W_last1 = (const float*)d_in[12];
    const float* b_last1 = (const float*)d_in[13];
    const float* W_last2 = (const float*)d_in[14];
    const float* b_last2 = (const float*)d_in[15];
    float* out = (float*)d_out;

    cudaFuncSetAttribute(first_kernel,  cudaFuncAttributeMaxDynamicSharedMemorySize, FIRST_SMEM);
    cudaFuncSetAttribute(gate_kernel,   cudaFuncAttributeMaxDynamicSharedMemorySize, GATE_SMEM);
    cudaFuncSetAttribute(skipout_kernel,cudaFuncAttributeMaxDynamicSharedMemorySize, SKIPOUT_SMEM);
    cudaFuncSetAttribute(dense256_kernel,cudaFuncAttributeMaxDynamicSharedMemorySize, DENSE_SMEM);

    int dev = 0;
    cudaGetDevice(&dev);
    int sm_count = 148;
    cudaDeviceGetAttribute(&sm_count, cudaDevAttrMultiProcessorCount, dev);
    int grid1 = sm_count;
    int grid2 = 2 * sm_count;

    first_kernel<<<grid1, 256, FIRST_SMEM>>>(x, W_first, b_first);

    for (int l = 0; l < 20; l++) {
        int dil = 1 << (l % 10);
        int hsel = l & 1;
        gate_kernel<<<grid1, 512, GATE_SMEM>>>(l, dil, hsel, c,
                                               W_dil, b_dil, W_c, b_c);
        skipout_kernel<<<grid1, 512, SKIPOUT_SMEM>>>(l, hsel,
                                                     W_skip, b_skip, W_out, b_out);
    }

    dense256_kernel<<<grid2, 512, DENSE_SMEM>>>(0, out, W_last1, b_last1);
    dense256_kernel<<<grid2, 512, DENSE_SMEM>>>(1, out, W_last2, b_last2);
}

// round 10
// speedup vs baseline: 1.9578x; 1.1323x over previous
#include <cuda_runtime.h>
#include <cuda_bf16.h>
#include <stdint.h>
#include <math.h>

#define T_LEN 16384
#define NB 4

static __device__ __forceinline__ float sigmoidf_(float v) {
    return 1.0f / (1.0f + __expf(-v));
}

#define SQRT_HALF_F 0.70710678118654752f

// bf16 HMMA m16n8k16 (base-target PTX)
static __device__ __forceinline__ void mma_bf16(
    float* d, uint32_t a0, uint32_t a1, uint32_t a2, uint32_t a3,
    uint32_t b0, uint32_t b1)
{
    asm volatile(
        "mma.sync.aligned.m16n8k16.row.col.f32.bf16.bf16.f32 "
        "{%0,%1,%2,%3}, {%4,%5,%6,%7}, {%8,%9}, {%0,%1,%2,%3};"
        : "+f"(d[0]), "+f"(d[1]), "+f"(d[2]), "+f"(d[3])
        : "r"(a0), "r"(a1), "r"(a2), "r"(a3), "r"(b0), "r"(b1));
}
// ldmatrix x4 (base PTX sm_75+)
static __device__ __forceinline__ void ldsm_x4(uint32_t* r, uint32_t addr) {
    asm volatile(
        "ldmatrix.sync.aligned.m8n8.x4.shared.b16 {%0,%1,%2,%3}, [%4];"
        : "=r"(r[0]), "=r"(r[1]), "=r"(r[2]), "=r"(r[3]) : "r"(addr));
}
static __device__ __forceinline__ uint32_t pk_bf2(float a, float b) {
    __nv_bfloat162 t;
    t.x = __float2bfloat16(a);
    t.y = __float2bfloat16(b);
    return *(uint32_t*)&t;
}
static __device__ __forceinline__ uint32_t smem_u32(const void* p) {
    uint32_t a;
    asm("{ .reg .u64 t; cvta.to.shared.u64 t, %1; cvt.u32.u64 %0, t; }"
        : "=r"(a) : "l"(p));
    return a;
}

// ---------------- scratch (allocation-free: __device__ globals) ----------------
__device__ float g_h[2][NB * 64 * T_LEN];     // residual ping-pong
__device__ float g_z[NB * 64 * T_LEN];        // gated activations per layer
__device__ float g_skip[NB * 256 * T_LEN];    // skip accumulator
__device__ float g_tmp[NB * 256 * T_LEN];     // final intermediate
// prepped dense weights: [stage][chunk][oc*136 + klocal]
__device__ __nv_bfloat16 g_dwh[2][2][256 * 136];
__device__ __nv_bfloat16 g_dwl[2][2][256 * 136];

// =======================================================================
// Kernel 0: prep dense weights (fp32 -> bf16 hi/lo, chunked layout)
// =======================================================================
__global__ void prep_dense_kernel(const float* __restrict__ W1,
                                  const float* __restrict__ W2)
{
    int i = blockIdx.x * blockDim.x + threadIdx.x;
    if (i >= 2 * 256 * 256) return;
    int stage = i >> 16;
    int oc = (i >> 8) & 255;
    int k = i & 255;
    float w = (stage ? W2 : W1)[oc * 256 + k];
    __nv_bfloat16 wh = __float2bfloat16(w);
    int chunk = k >> 7, kl = k & 127;
    g_dwh[stage][chunk][oc * 136 + kl] = wh;
    g_dwl[stage][chunk][oc * 136 + kl] = __float2bfloat16(w - __bfloat162float(wh));
}

// =======================================================================
// Kernel 1: first conv (k=2 causal, 256 -> 64) + tanh. (unchanged)
// =======================================================================
#define FIRST_SMEM 200960
__global__ __launch_bounds__(256) void first_kernel(
    const float* __restrict__ x, const float* __restrict__ Wf,
    const float* __restrict__ bf)
{
    extern __shared__ float sm[];
    float* Wf_s = sm;
    float* bs   = Wf_s + 32768;
    float* Xs   = bs + 64;

    int tid = threadIdx.x;
    for (int i = tid; i < 64 * 256 * 2; i += 256) {
        int oc = i >> 9; int ic = (i >> 1) & 255; int k = i & 1;
        Wf_s[ic * 128 + k * 64 + oc] = Wf[i];
    }
    if (tid < 64) bs[tid] = bf[tid];
    __syncthreads();

    int tq = tid & 7, grp = tid >> 3;
    int tb = tq * 8, oc2 = grp * 2;

    for (int tile = blockIdx.x; tile < NB * 256; tile += gridDim.x) {
        int b = tile >> 8;
        int t0 = (tile & 255) << 6;
        __syncthreads();
        for (int i = tid; i < 256 * 65; i += 256) {
            int ic = i / 65, jj = i - ic * 65;
            int t = (jj < 64) ? (t0 + jj) : (t0 - 1);
            Xs[ic * 68 + jj] = (t >= 0) ? x[((b * 256 + ic) << 14) + t] : 0.f;
        }
        __syncthreads();

        float acc[2][8];
#pragma unroll
        for (int a = 0; a < 2; a++)
#pragma unroll
            for (int j = 0; j < 8; j++) acc[a][j] = 0.f;

#pragma unroll 2
        for (int ic = 0; ic < 256; ic++) {
            const float* xp = Xs + ic * 68 + tb;
            float4 x0 = *(const float4*)xp;
            float4 x1 = *(const float4*)(xp + 4);
            float xm1 = (tb == 0) ? Xs[ic * 68 + 64] : Xs[ic * 68 + tb - 1];
            float2 w0 = *(const float2*)(Wf_s + ic * 128 + oc2);
            float2 w1 = *(const float2*)(Wf_s + ic * 128 + 64 + oc2);
            float xc[8] = {x0.x, x0.y, x0.z, x0.w, x1.x, x1.y, x1.z, x1.w};
            float xpv[8] = {xm1, xc[0], xc[1], xc[2], xc[3], xc[4], xc[5], xc[6]};
            float wa[2] = {w0.x, w0.y};
            float wb[2] = {w1.x, w1.y};
#pragma unroll
            for (int a = 0; a < 2; a++)
#pragma unroll
                for (int j = 0; j < 8; j++)
                    acc[a][j] += wa[a] * xpv[j] + wb[a] * xc[j];
        }

#pragma unroll
        for (int a = 0; a < 2; a++) {
            int oc = oc2 + a;
            float bv = bs[oc];
            float* hp = &g_h[0][((b * 64 + oc) << 14) + t0 + tb];
            float4 v0, v1;
            v0.x = tanhf(acc[a][0] + bv); v0.y = tanhf(acc[a][1] + bv);
            v0.z = tanhf(acc[a][2] + bv); v0.w = tanhf(acc[a][3] + bv);
            v1.x = tanhf(acc[a][4] + bv); v1.y = tanhf(acc[a][5] + bv);
            v1.z = tanhf(acc[a][6] + bv); v1.w = tanhf(acc[a][7] + bv);
            *(float4*)hp = v0;
            *(float4*)(hp + 4) = v1;
        }
    }
}

// =======================================================================
// Kernel 2 (v7 — HMMA + ldmatrix, fused hi/lo): gate. (unchanged from R9)
// =======================================================================
#define GATE_SMEM 222208
__global__ __launch_bounds__(512) void gate_kernel(
    int layer, int dil, int hsel,
    const float* __restrict__ c,
    const float* __restrict__ W_dil, const float* __restrict__ b_dil,
    const float* __restrict__ W_c, const float* __restrict__ b_c)
{
    extern __shared__ float smf[];
    char* smem = (char*)smf;

    int tid = threadIdx.x;
    int lane = tid & 31, warp = tid >> 5;
    const float* Wd = W_dil + layer * 24576;
    const float* Wc = W_c + layer * 10240;
    const float* h_in = g_h[hsel];

    __nv_bfloat16* Ah_s = (__nv_bfloat16*)(smem + 1024);
    __nv_bfloat16* Al_s = (__nv_bfloat16*)(smem + 72704);
    __nv_bfloat16* Bh_s = (__nv_bfloat16*)(smem + 144384);
    __nv_bfloat16* Bl_s = (__nv_bfloat16*)(smem + 183296);
    float* ys = (float*)(smem + 144384);    // overlay on B region

    if (tid < 128) {
        int g = (tid & 1) ? 64 + (tid >> 1) : (tid >> 1);
        smf[tid] = b_dil[layer * 128 + g] + b_c[layer * 128 + g];
    }
    for (int i = tid; i < 128 * 272; i += 512) {
        int pg = i / 272, k = i - pg * 272;
        int g = (pg & 1) ? 64 + (pg >> 1) : (pg >> 1);
        float w = (k < 192) ? Wd[g * 192 + (k & 63) * 3 + (k >> 6)]
                            : Wc[g * 80 + (k - 192)];
        __nv_bfloat16 wh = __float2bfloat16(w);
        Ah_s[pg * 280 + k] = wh;
        Al_s[pg * 280 + k] = __float2bfloat16(w - __bfloat162float(wh));
    }
    __syncthreads();

    int m0 = (warp & 7) * 16;
    int n0 = (warp >> 3) * 64;
    int r0 = m0 + (lane >> 2);
    int q = (lane & 3) * 2;

    uint32_t sb = smem_u32(smem);
    uint32_t aBase = sb + 1024 +
        (uint32_t)(((m0 + (lane & 15)) * 280 + (lane >> 4) * 8) * 2);
    const uint32_t A_LO = 71680;
    uint32_t bBase[4];
#pragma unroll
    for (int p = 0; p < 4; p++) {
        int n = n0 + ((lane >> 4) & 1) * 8 + (lane & 7) + 16 * p;
        bBase[p] = sb + 144384 + (uint32_t)((n * 152) * 2 + (lane & 8) * 2);
    }
    const uint32_t B_LO = 38912;

    for (int tile = blockIdx.x; tile < NB * 128; tile += gridDim.x) {
        int b = tile >> 7;
        int t0 = (tile & 127) << 7;

        float d[8][4];
#pragma unroll
        for (int nt = 0; nt < 8; nt++)
#pragma unroll
            for (int e = 0; e < 4; e++) d[nt][e] = 0.f;

#pragma unroll 1
        for (int chunk = 0; chunk < 2; chunk++) {
            int ug0 = chunk ? 18 : 0;
            int ug1 = chunk ? 34 : 18;
            for (int u = ug0 * 4 + warp; u < ug1 * 4; u += 16) {
                int kg = u >> 2, nb = u & 3;
                int n = (nb << 5) + lane;
                int t = t0 + n;
                float v[8];
                if (kg < 24) {
                    int tap = kg >> 3, rb = (kg & 7) << 3;
                    int ts = t - (2 - tap) * dil;
                    const float* hp = h_in + ((b * 64 + rb) << 14) + ts;
                    if (ts >= 0) {
#pragma unroll
                        for (int j = 0; j < 8; j++) v[j] = hp[j << 14];
                    } else {
#pragma unroll
                        for (int j = 0; j < 8; j++) v[j] = 0.f;
                    }
                } else {
                    int cb = (kg - 24) << 3;
                    const float* cp = c + ((b * 80 + cb) << 14) + t;
#pragma unroll
                    for (int j = 0; j < 8; j++) v[j] = cp[j << 14];
                }
                uint32_t ph[4], pl[4];
#pragma unroll
                for (int m = 0; m < 4; m++) {
                    float a0 = v[2 * m], a1 = v[2 * m + 1];
                    __nv_bfloat16 h0 = __float2bfloat16(a0);
                    __nv_bfloat16 h1 = __float2bfloat16(a1);
                    ph[m] = pk_bf2(a0, a1);
                    pl[m] = pk_bf2(a0 - __bfloat162float(h0),
                                   a1 - __bfloat162float(h1));
                }
                int klocal = kg * 8 - (chunk ? 144 : 0);
                *(uint4*)(Bh_s + n * 152 + klocal) = make_uint4(ph[0], ph[1], ph[2], ph[3]);
                *(uint4*)(Bl_s + n * 152 + klocal) = make_uint4(pl[0], pl[1], pl[2], pl[3]);
            }
            __syncthreads();

            int nk = chunk ? 8 : 9;
            int kAbase = chunk ? 144 : 0;
#pragma unroll 1
            for (int ks = 0; ks < nk; ks++) {
                uint32_t offA = (uint32_t)((kAbase + ks * 16) * 2);
                uint32_t offB = (uint32_t)(ks * 16 * 2);
                uint32_t ah[4], al[4];
                ldsm_x4(ah, aBase + offA);
                ldsm_x4(al, aBase + A_LO + offA);
#pragma unroll
                for (int p = 0; p < 4; p++) {
                    uint32_t bh[4], bl[4];
                    ldsm_x4(bh, bBase[p] + offB);
                    ldsm_x4(bl, bBase[p] + B_LO + offB);
                    int e0 = 2 * p, e1 = 2 * p + 1;
                    mma_bf16(d[e0], ah[0], ah[1], ah[2], ah[3], bh[0], bh[1]);
                    mma_bf16(d[e0], ah[0], ah[1], ah[2], ah[3], bl[0], bl[1]);
                    mma_bf16(d[e0], al[0], al[1], al[2], al[3], bh[0], bh[1]);
                    mma_bf16(d[e1], ah[0], ah[1], ah[2], ah[3], bh[2], bh[3]);
                    mma_bf16(d[e1], ah[0], ah[1], ah[2], ah[3], bl[2], bl[3]);
                    mma_bf16(d[e1], al[0], al[1], al[2], al[3], bh[2], bh[3]);
                }
            }
            __syncthreads();
        }

#pragma unroll
        for (int nt = 0; nt < 8; nt++) {
            int col = n0 + nt * 8 + q;
            *(float2*)(ys + r0 * 132 + col)       = make_float2(d[nt][0], d[nt][1]);
            *(float2*)(ys + (r0 + 8) * 132 + col) = make_float2(d[nt][2], d[nt][3]);
        }
        __syncthreads();

        {
            int i = tid >> 3;
            int qb = tid & 7;
            float ba = smf[2 * i], bb = smf[2 * i + 1];
            const float* ya = ys + (2 * i) * 132 + qb * 16;
            const float* yb = ys + (2 * i + 1) * 132 + qb * 16;
            float* zp = &g_z[((b * 64 + i) << 14) + t0 + qb * 16];
#pragma unroll
            for (int e = 0; e < 4; e++) {
                float4 av = *(const float4*)(ya + e * 4);
                float4 bv = *(const float4*)(yb + e * 4);
                float4 zv;
                zv.x = tanhf(av.x + ba) * sigmoidf_(bv.x + bb);
                zv.y = tanhf(av.y + ba) * sigmoidf_(bv.y + bb);
                zv.z = tanhf(av.z + ba) * sigmoidf_(bv.z + bb);
                zv.w = tanhf(av.w + ba) * sigmoidf_(bv.w + bb);
                *(float4*)(zp + e * 4) = zv;
            }
        }
        __syncthreads();
    }
}

// =======================================================================
// Kernel 3 (v5 — HMMA + ldmatrix, fused hi/lo): skip+out. (unchanged R9)
// =======================================================================
#define SKIPOUT_SMEM 204288
__global__ __launch_bounds__(512) void skipout_kernel(
    int layer, int hsel,
    const float* __restrict__ W_skip, const float* __restrict__ b_skip,
    const float* __restrict__ W_out, const float* __restrict__ b_out)
{
    extern __shared__ float smf[];
    char* smem = (char*)smf;

    int tid = threadIdx.x;
    int lane = tid & 31, warp = tid >> 5;
    const float* Wsk = W_skip + layer * 256 * 64;
    const float* Wo  = W_out + layer * 64 * 64;
    const float* h_in = g_h[hsel];
    float* h_out = g_h[1 - hsel];

    float* bsk_s = smf;
    float* bo_s  = smf + 256;
    __nv_bfloat16* Ah = (__nv_bfloat16*)(smem + 1536);
    __nv_bfloat16* Al = (__nv_bfloat16*)(smem + 57856);
    __nv_bfloat16* Bh = (__nv_bfloat16*)(smem + 114176);
    __nv_bfloat16* Bl = (__nv_bfloat16*)(smem + 159232);
    const uint32_t A_LO = 56320, B_LO = 45056;

    if (tid < 256) bsk_s[tid] = b_skip[layer * 256 + tid];
    if (tid < 64)  bo_s[tid]  = b_out[layer * 64 + tid];

    for (int i = tid; i < 320 * 64; i += 512) {
        int m = i >> 6, k = i & 63;
        float w = (m < 256) ? Wsk[(m << 6) + k] : Wo[((m - 256) << 6) + k];
        __nv_bfloat16 wh = __float2bfloat16(w);
        Ah[m * 88 + k] = wh;
        Al[m * 88 + k] = __float2bfloat16(w - __bfloat162float(wh));
    }
    __syncthreads();

    int q = (lane & 3) * 2;
    int rl = lane >> 2;
    uint32_t sb = smem_u32(smem);
    uint32_t aLaneOff = (uint32_t)(((lane & 15) * 88 + (lane >> 4) * 8) * 2);
    uint32_t bLaneOff = (uint32_t)(((((lane >> 4) & 1) * 8 + (lane & 7)) * 88) * 2
                                   + (lane & 8) * 2);

    for (int tile = blockIdx.x; tile < NB * 64; tile += gridDim.x) {
        int b = tile >> 6;
        int t0 = (tile & 63) << 8;

        for (int u = warp; u < 64; u += 16) {
            int kg = u >> 3, nb = u & 7;
            int n = (nb << 5) + lane;
            int t = t0 + n;
            const float* zp = g_z + ((b * 64 + kg * 8) << 14) + t;
            float v[8];
#pragma unroll
            for (int j = 0; j < 8; j++) v[j] = zp[j << 14];
            uint32_t ph[4], pl[4];
#pragma unroll
            for (int m = 0; m < 4; m++) {
                float a0 = v[2 * m], a1 = v[2 * m + 1];
                __nv_bfloat16 h0 = __float2bfloat16(a0);
                __nv_bfloat16 h1 = __float2bfloat16(a1);
                ph[m] = pk_bf2(a0, a1);
                pl[m] = pk_bf2(a0 - __bfloat162float(h0),
                               a1 - __bfloat162float(h1));
            }
            *(uint4*)(Bh + n * 88 + kg * 8) = make_uint4(ph[0], ph[1], ph[2], ph[3]);
            *(uint4*)(Bl + n * 88 + kg * 8) = make_uint4(pl[0], pl[1], pl[2], pl[3]);
        }
        __syncthreads();

        for (int u = warp; u < 80; u += 16) {
            int mt = u >> 2, ng = u & 3;
            int m0 = mt << 4, n0g = ng << 6;
            int r0 = m0 + rl;

            uint32_t aBase = sb + 1536 + (uint32_t)(m0 * 88 * 2) + aLaneOff;
            uint32_t bBase = sb + 114176 + (uint32_t)(n0g * 88 * 2) + bLaneOff;

            float d[8][4];
#pragma unroll
            for (int nt = 0; nt < 8; nt++)
#pragma unroll
                for (int e = 0; e < 4; e++) d[nt][e] = 0.f;

#pragma unroll
            for (int ks = 0; ks < 4; ks++) {
                uint32_t off = (uint32_t)(ks * 16 * 2);
                uint32_t ah[4], al[4];
                ldsm_x4(ah, aBase + off);
                ldsm_x4(al, aBase + A_LO + off);
#pragma unroll
                for (int p = 0; p < 4; p++) {
                    uint32_t bh[4], bl[4];
                    uint32_t bp = bBase + (uint32_t)(16 * p * 88 * 2) + off;
                    ldsm_x4(bh, bp);
                    ldsm_x4(bl, bp + B_LO);
                    int e0 = 2 * p, e1 = 2 * p + 1;
                    mma_bf16(d[e0], ah[0], ah[1], ah[2], ah[3], bh[0], bh[1]);
                    mma_bf16(d[e0], ah[0], ah[1], ah[2], ah[3], bl[0], bl[1]);
                    mma_bf16(d[e0], al[0], al[1], al[2], al[3], bh[0], bh[1]);
                    mma_bf16(d[e1], ah[0], ah[1], ah[2], ah[3], bh[2], bh[3]);
                    mma_bf16(d[e1], ah[0], ah[1], ah[2], ah[3], bl[2], bl[3]);
                    mma_bf16(d[e1], al[0], al[1], al[2], al[3], bh[2], bh[3]);
                }
            }

            if (m0 < 256) {
#pragma unroll
                for (int hh = 0; hh < 2; hh++) {
                    int sc = r0 + hh * 8;
                    float bsv = bsk_s[sc];
                    float* sp = &g_skip[((b * 256 + sc) << 14) + t0 + n0g + q];
                    if (layer == 0) {
#pragma unroll
                        for (int nt = 0; nt < 8; nt++) {
                            *(float2*)(sp + nt * 8) =
                                make_float2(d[nt][hh * 2] + bsv, d[nt][hh * 2 + 1] + bsv);
                        }
                    } else {
#pragma unroll
                        for (int nt = 0; nt < 8; nt++) {
                            float2 o = *(float2*)(sp + nt * 8);
                            *(float2*)(sp + nt * 8) = make_float2(
                                (o.x + d[nt][hh * 2] + bsv) * SQRT_HALF_F,
                                (o.y + d[nt][hh * 2 + 1] + bsv) * SQRT_HALF_F);
                        }
                    }
                }
            } else {
#pragma unroll
                for (int hh = 0; hh < 2; hh++) {
                    int oc = r0 - 256 + hh * 8;
                    float bov = bo_s[oc];
                    const float* hip = h_in + ((b * 64 + oc) << 14) + t0 + n0g + q;
                    float* hop = h_out + ((b * 64 + oc) << 14) + t0 + n0g + q;
#pragma unroll
                    for (int nt = 0; nt < 8; nt++) {
                        float2 hv = *(const float2*)(hip + nt * 8);
                        *(float2*)(hop + nt * 8) = make_float2(
                            (d[nt][hh * 2] + bov + hv.x) * SQRT_HALF_F,
                            (d[nt][hh * 2 + 1] + bov + hv.y) * SQRT_HALF_F);
                    }
                }
            }
        }
        __syncthreads();
    }
}

// =======================================================================
// Kernel 4 (v4 — HMMA + ldmatrix): dense 256x256, prepped weights.
//   Tile = 256 oc x 128 t, K=256 in 2 chunks of 128.
//   Warp = one 16-row m-tile across all 128 t (A frags shared, 8 n-pairs).
// SMEM (bytes): bias 1024 | A_hi [256][136] 69632 @1024 | A_lo @70656
//               B_hi [128][136] 34816 @140288 | B_lo @175104 => 209920
// =======================================================================
#define DENSE_SMEM 209920
__global__ __launch_bounds__(512) void dense_hmma_kernel(
    int stage, float* __restrict__ final_out, const float* __restrict__ bias)
{
    extern __shared__ float smf[];
    char* smem = (char*)smf;

    int tid = threadIdx.x;
    int lane = tid & 31, warp = tid >> 5;

    const float* in = (stage == 0) ? g_skip : g_tmp;
    float* out = (stage == 0) ? g_tmp : final_out;

    float* bb = smf;   // 256
    __nv_bfloat16* AhS = (__nv_bfloat16*)(smem + 1024);
    __nv_bfloat16* AlS = (__nv_bfloat16*)(smem + 70656);
    __nv_bfloat16* BhS = (__nv_bfloat16*)(smem + 140288);
    __nv_bfloat16* BlS = (__nv_bfloat16*)(smem + 175104);
    const uint32_t A_LO = 69632, B_LO = 34816;

    if (tid < 256) bb[tid] = bias[tid];

    int mt = warp;               // m-tile 0..15
    int q = (lane & 3) * 2;
    int rl = lane >> 2;

    uint32_t sb = smem_u32(smem);
    uint32_t aBase = sb + 1024 +
        (uint32_t)(((mt * 16 + (lane & 15)) * 136 + (lane >> 4) * 8) * 2);
    uint32_t bBase[8];
#pragma unroll
    for (int p = 0; p < 8; p++) {
        int n = ((lane >> 4) & 1) * 8 + (lane & 7) + 16 * p;
        bBase[p] = sb + 140288 + (uint32_t)((n * 136) * 2 + (lane & 8) * 2);
    }

    for (int tile = blockIdx.x; tile < NB * 128; tile += gridDim.x) {
        int b = tile >> 7;
        int t0 = (tile & 127) << 7;

        float d[16][4];
#pragma unroll
        for (int nt = 0; nt < 16; nt++)
#pragma unroll
            for (int e = 0; e < 4; e++) d[nt][e] = 0.f;

#pragma unroll 1
        for (int chunk = 0; chunk < 2; chunk++) {
            __syncthreads();   // prev chunk's reads / prev tile done
            // ---- stage A chunk: flat uint4 copies of prepped weights ----
            {
                const uint4* gh = (const uint4*)g_dwh[stage][chunk];
                const uint4* gl = (const uint4*)g_dwl[stage][chunk];
                uint4* sh = (uint4*)AhS;
                uint4* sl = (uint4*)AlS;
                for (int i = tid; i < 4352; i += 512) {
                    sh[i] = gh[i];
                    sl[i] = gl[i];
                }
            }
            // ---- stage B chunk: convert activations (relu for stage 0) ----
            for (int u = warp; u < 64; u += 16) {
                int kg = u >> 2, nb = u & 3;
                int n = (nb << 5) + lane;
                int t = t0 + n;
                const float* ip = in + ((b * 256 + chunk * 128 + kg * 8) << 14) + t;
                float v[8];
#pragma unroll
                for (int j = 0; j < 8; j++) {
                    float x = ip[j << 14];
                    v[j] = (stage == 0) ? fmaxf(x, 0.f) : x;
                }
                uint32_t ph[4], pl[4];
#pragma unroll
                for (int m = 0; m < 4; m++) {
                    float a0 = v[2 * m], a1 = v[2 * m + 1];
                    __nv_bfloat16 h0 = __float2bfloat16(a0);
                    __nv_bfloat16 h1 = __float2bfloat16(a1);
                    ph[m] = pk_bf2(a0, a1);
                    pl[m] = pk_bf2(a0 - __bfloat162float(h0),
                                   a1 - __bfloat162float(h1));
                }
                *(uint4*)(BhS + n * 136 + kg * 8) = make_uint4(ph[0], ph[1], ph[2], ph[3]);
                *(uint4*)(BlS + n * 136 + kg * 8) = make_uint4(pl[0], pl[1], pl[2], pl[3]);
            }
            __syncthreads();

            // ---- HMMA: 8 k-steps, A frags shared across 8 n-pairs ----
#pragma unroll 1
            for (int ks = 0; ks < 8; ks++) {
                uint32_t off = (uint32_t)(ks * 16 * 2);
                uint32_t ah[4], al[4];
                ldsm_x4(ah, aBase + off);
                ldsm_x4(al, aBase + A_LO + off);
#pragma unroll
                for (int p = 0; p < 8; p++) {
                    uint32_t bh[4], bl[4];
                    ldsm_x4(bh, bBase[p] + off);
                    ldsm_x4(bl, bBase[p] + B_LO + off);
                    int e0 = 2 * p, e1 = 2 * p + 1;
                    mma_bf16(d[e0], ah[0], ah[1], ah[2], ah[3], bh[0], bh[1]);
                    mma_bf16(d[e0], ah[0], ah[1], ah[2], ah[3], bl[0], bl[1]);
                    mma_bf16(d[e0], al[0], al[1], al[2], al[3], bh[0], bh[1]);
                    mma_bf16(d[e1], ah[0], ah[1], ah[2], ah[3], bh[2], bh[3]);
                    mma_bf16(d[e1], ah[0], ah[1], ah[2], ah[3], bl[2], bl[3]);
                    mma_bf16(d[e1], al[0], al[1], al[2], al[3], bh[2], bh[3]);
                }
            }
        }

        // ---- epilogue straight from registers ----
#pragma unroll
        for (int hh = 0; hh < 2; hh++) {
            int oc = mt * 16 + rl + hh * 8;
            float bv = bb[oc];
            float* op = out + ((b * 256 + oc) << 14) + t0;
#pragma unroll
            for (int nt = 0; nt < 16; nt++) {
                int col = (nt >> 1) * 16 + (nt & 1) * 8 + q;
                float2 v = make_float2(d[nt][hh * 2] + bv, d[nt][hh * 2 + 1] + bv);
                if (stage == 0) {
                    v.x = fmaxf(v.x, 0.f);
                    v.y = fmaxf(v.y, 0.f);
                }
                *(float2*)(op + col) = v;
            }
        }
    }
}

// =======================================================================
extern "C" void kernel_launch(void* const* d_in, const int* in_sizes, int n_in,
                              void* d_out, int out_size)
{
    const float* x       = (const float*)d_in[0];
    const float* c       = (const float*)d_in[1];
    const float* W_first = (const float*)d_in[2];
    const float* b_first = (const float*)d_in[3];
    const float* W_dil   = (const float*)d_in[4];
    const float* b_dil   = (const float*)d_in[5];
    const float* W_c     = (const float*)d_in[6];
    const float* b_c     = (const float*)d_in[7];
    const float* W_skip  = (const float*)d_in[8];
    const float* b_skip  = (const float*)d_in[9];
    const float* W_out   = (const float*)d_in[10];
    const float* b_out   = (const float*)d_in[11];
    const float* W_last1 = (const float*)d_in[12];
    const float* b_last1 = (const float*)d_in[13];
    const float* W_last2 = (const float*)d_in[14];
    const float* b_last2 = (const float*)d_in[15];
    float* out = (float*)d_out;

    cudaFuncSetAttribute(first_kernel,  cudaFuncAttributeMaxDynamicSharedMemorySize, FIRST_SMEM);
    cudaFuncSetAttribute(gate_kernel,   cudaFuncAttributeMaxDynamicSharedMemorySize, GATE_SMEM);
    cudaFuncSetAttribute(skipout_kernel,cudaFuncAttributeMaxDynamicSharedMemorySize, SKIPOUT_SMEM);
    cudaFuncSetAttribute(dense_hmma_kernel,cudaFuncAttributeMaxDynamicSharedMemorySize, DENSE_SMEM);

    int dev = 0;
    cudaGetDevice(&dev);
    int sm_count = 148;
    cudaDeviceGetAttribute(&sm_count, cudaDevAttrMultiProcessorCount, dev);
    int grid1 = sm_count;

    prep_dense_kernel<<<256, 512>>>(W_last1, W_last2);
    first_kernel<<<grid1, 256, FIRST_SMEM>>>(x, W_first, b_first);

    for (int l = 0; l < 20; l++) {
        int dil = 1 << (l % 10);
        int hsel = l & 1;
        gate_kernel<<<grid1, 512, GATE_SMEM>>>(l, dil, hsel, c,
                                               W_dil, b_dil, W_c, b_c);
        skipout_kernel<<<grid1, 512, SKIPOUT_SMEM>>>(l, hsel,
                                                     W_skip, b_skip, W_out, b_out);
    }

    dense_hmma_kernel<<<grid1, 512, DENSE_SMEM>>>(0, out, b_last1);
    dense_hmma_kernel<<<grid1, 512, DENSE_SMEM>>>(1, out, b_last2);
}

// round 11
// speedup vs baseline: 2.0502x; 1.0472x over previous
#include <cuda_runtime.h>
#include <cuda_bf16.h>
#include <stdint.h>
#include <math.h>

#define T_LEN 16384
#define NB 4

static __device__ __forceinline__ float sigmoidf_(float v) {
    return 1.0f / (1.0f + __expf(-v));
}

#define SQRT_HALF_F 0.70710678118654752f

// bf16 HMMA m16n8k16 (base-target PTX)
static __device__ __forceinline__ void mma_bf16(
    float* d, uint32_t a0, uint32_t a1, uint32_t a2, uint32_t a3,
    uint32_t b0, uint32_t b1)
{
    asm volatile(
        "mma.sync.aligned.m16n8k16.row.col.f32.bf16.bf16.f32 "
        "{%0,%1,%2,%3}, {%4,%5,%6,%7}, {%8,%9}, {%0,%1,%2,%3};"
        : "+f"(d[0]), "+f"(d[1]), "+f"(d[2]), "+f"(d[3])
        : "r"(a0), "r"(a1), "r"(a2), "r"(a3), "r"(b0), "r"(b1));
}
// ldmatrix x4 (base PTX sm_75+)
static __device__ __forceinline__ void ldsm_x4(uint32_t* r, uint32_t addr) {
    asm volatile(
        "ldmatrix.sync.aligned.m8n8.x4.shared.b16 {%0,%1,%2,%3}, [%4];"
        : "=r"(r[0]), "=r"(r[1]), "=r"(r[2]), "=r"(r[3]) : "r"(addr));
}
static __device__ __forceinline__ uint32_t pk_bf2(float a, float b) {
    __nv_bfloat162 t;
    t.x = __float2bfloat16(a);
    t.y = __float2bfloat16(b);
    return *(uint32_t*)&t;
}
static __device__ __forceinline__ uint32_t smem_u32(const void* p) {
    uint32_t a;
    asm("{ .reg .u64 t; cvta.to.shared.u64 t, %1; cvt.u32.u64 %0, t; }"
        : "=r"(a) : "l"(p));
    return a;
}

// ---------------- scratch (allocation-free: __device__ globals) ----------------
__device__ float g_h[2][NB * 64 * T_LEN];     // residual ping-pong
__device__ float g_z[NB * 64 * T_LEN];        // gated activations per layer
__device__ float g_skip[NB * 256 * T_LEN];    // skip accumulator
__device__ float g_tmp[NB * 256 * T_LEN];     // final intermediate
// prepped dense weights: [stage][chunk][oc*136 + klocal]
__device__ __nv_bfloat16 g_dwh[2][2][256 * 136];
__device__ __nv_bfloat16 g_dwl[2][2][256 * 136];

// =======================================================================
// Kernel 0: prep dense weights (fp32 -> bf16 hi/lo, chunked layout)
// =======================================================================
__global__ void prep_dense_kernel(const float* __restrict__ W1,
                                  const float* __restrict__ W2)
{
    int i = blockIdx.x * blockDim.x + threadIdx.x;
    if (i >= 2 * 256 * 256) return;
    int stage = i >> 16;
    int oc = (i >> 8) & 255;
    int k = i & 255;
    float w = (stage ? W2 : W1)[oc * 256 + k];
    __nv_bfloat16 wh = __float2bfloat16(w);
    int chunk = k >> 7, kl = k & 127;
    g_dwh[stage][chunk][oc * 136 + kl] = wh;
    g_dwl[stage][chunk][oc * 136 + kl] = __float2bfloat16(w - __bfloat162float(wh));
}

// =======================================================================
// Kernel 1 (v2 — HMMA + ldmatrix): first conv (k=2 causal, 256->64) + tanh.
//   GEMM: M=64 oc, K=512 (ic*2+tap), N=65536 t. B[n][kg]=x[ic][t-1+tap].
//   A (all 4 K-chunks) staged once; B (128-t tile) restaged per 128-K chunk.
// SMEM: bias @0 (1024) | A_hi [4][64][136] 69632 @1024 | A_lo @70656
//       B_hi [128][136] 34816 @140288 | B_lo @175104 => 209920
// =======================================================================
#define FIRST_SMEM 209920
__global__ __launch_bounds__(512) void first_hmma_kernel(
    const float* __restrict__ x, const float* __restrict__ Wf,
    const float* __restrict__ bf)
{
    extern __shared__ float smf[];
    char* smem = (char*)smf;

    int tid = threadIdx.x;
    int lane = tid & 31, warp = tid >> 5;

    float* bb = smf;    // 64
    __nv_bfloat16* AhS = (__nv_bfloat16*)(smem + 1024);
    __nv_bfloat16* AlS = (__nv_bfloat16*)(smem + 70656);
    __nv_bfloat16* BhS = (__nv_bfloat16*)(smem + 140288);
    __nv_bfloat16* BlS = (__nv_bfloat16*)(smem + 175104);
    const uint32_t A_LO = 69632, B_LO = 34816;

    if (tid < 64) bb[tid] = bf[tid];
    // stage A (64 x 512, hi/lo), chunked [chunk][oc][136]
    for (int i = tid; i < 64 * 512; i += 512) {
        int oc = i >> 9, k = i & 511;
        int chunk = k >> 7, kl = k & 127;
        float w = Wf[oc * 512 + k];
        __nv_bfloat16 wh = __float2bfloat16(w);
        AhS[(chunk * 64 + oc) * 136 + kl] = wh;
        AlS[(chunk * 64 + oc) * 136 + kl] = __float2bfloat16(w - __bfloat162float(wh));
    }
    __syncthreads();

    int mt = warp & 3;          // m-tile (16 oc)
    int tg = warp >> 2;         // n-group (32 t)
    int q = (lane & 3) * 2;
    int rl = lane >> 2;

    uint32_t sb = smem_u32(smem);
    uint32_t aBase = sb + 1024 +
        (uint32_t)(((mt * 16 + (lane & 15)) * 136 + (lane >> 4) * 8) * 2);
    uint32_t bBase[2];
#pragma unroll
    for (int p = 0; p < 2; p++) {
        int n = tg * 32 + ((lane >> 4) & 1) * 8 + (lane & 7) + 16 * p;
        bBase[p] = sb + 140288 + (uint32_t)((n * 136) * 2 + (lane & 8) * 2);
    }

    for (int tile = blockIdx.x; tile < NB * 128; tile += gridDim.x) {
        int b = tile >> 7;
        int t0 = (tile & 127) << 7;

        float d[4][4];
#pragma unroll
        for (int nt = 0; nt < 4; nt++)
#pragma unroll
            for (int e = 0; e < 4; e++) d[nt][e] = 0.f;

#pragma unroll 1
        for (int chunk = 0; chunk < 4; chunk++) {
            __syncthreads();   // prev chunk's B reads done
            // ---- stage B chunk: 16 kgroups x 4 nblocks = 64 units ----
            for (int u = warp; u < 64; u += 16) {
                int kgl = u >> 2, nb = u & 3;
                int n = (nb << 5) + lane;
                int t = t0 + n;
                float v[8];
#pragma unroll
                for (int j = 0; j < 8; j++) {
                    int kg = chunk * 128 + kgl * 8 + j;
                    int ic = kg >> 1, tap = kg & 1;
                    int ts = t - 1 + tap;
                    v[j] = (ts >= 0) ? x[((b * 256 + ic) << 14) + ts] : 0.f;
                }
                uint32_t ph[4], pl[4];
#pragma unroll
                for (int m = 0; m < 4; m++) {
                    float a0 = v[2 * m], a1 = v[2 * m + 1];
                    __nv_bfloat16 h0 = __float2bfloat16(a0);
                    __nv_bfloat16 h1 = __float2bfloat16(a1);
                    ph[m] = pk_bf2(a0, a1);
                    pl[m] = pk_bf2(a0 - __bfloat162float(h0),
                                   a1 - __bfloat162float(h1));
                }
                *(uint4*)(BhS + n * 136 + kgl * 8) = make_uint4(ph[0], ph[1], ph[2], ph[3]);
                *(uint4*)(BlS + n * 136 + kgl * 8) = make_uint4(pl[0], pl[1], pl[2], pl[3]);
            }
            __syncthreads();

            uint32_t choff = (uint32_t)(chunk * 64 * 136 * 2);
#pragma unroll 1
            for (int ks = 0; ks < 8; ks++) {
                uint32_t offA = choff + (uint32_t)(ks * 16 * 2);
                uint32_t offB = (uint32_t)(ks * 16 * 2);
                uint32_t ah[4], al[4];
                ldsm_x4(ah, aBase + offA);
                ldsm_x4(al, aBase + A_LO + offA);
#pragma unroll
                for (int p = 0; p < 2; p++) {
                    uint32_t bh[4], bl[4];
                    ldsm_x4(bh, bBase[p] + offB);
                    ldsm_x4(bl, bBase[p] + B_LO + offB);
                    int e0 = 2 * p, e1 = 2 * p + 1;
                    mma_bf16(d[e0], ah[0], ah[1], ah[2], ah[3], bh[0], bh[1]);
                    mma_bf16(d[e0], ah[0], ah[1], ah[2], ah[3], bl[0], bl[1]);
                    mma_bf16(d[e0], al[0], al[1], al[2], al[3], bh[0], bh[1]);
                    mma_bf16(d[e1], ah[0], ah[1], ah[2], ah[3], bh[2], bh[3]);
                    mma_bf16(d[e1], ah[0], ah[1], ah[2], ah[3], bl[2], bl[3]);
                    mma_bf16(d[e1], al[0], al[1], al[2], al[3], bh[2], bh[3]);
                }
            }
        }

        // ---- epilogue: tanh straight from registers ----
#pragma unroll
        for (int hh = 0; hh < 2; hh++) {
            int oc = mt * 16 + rl + hh * 8;
            float bv = bb[oc];
            float* hp = &g_h[0][((b * 64 + oc) << 14) + t0];
#pragma unroll
            for (int nt = 0; nt < 4; nt++) {
                int col = tg * 32 + (nt >> 1) * 16 + (nt & 1) * 8 + q;
                float2 v = make_float2(tanhf(d[nt][hh * 2] + bv),
                                       tanhf(d[nt][hh * 2 + 1] + bv));
                *(float2*)(hp + col) = v;
            }
        }
    }
}

// =======================================================================
// Kernel 2 (v7 — HMMA + ldmatrix, fused hi/lo): gate. (unchanged from R9)
// =======================================================================
#define GATE_SMEM 222208
__global__ __launch_bounds__(512) void gate_kernel(
    int layer, int dil, int hsel,
    const float* __restrict__ c,
    const float* __restrict__ W_dil, const float* __restrict__ b_dil,
    const float* __restrict__ W_c, const float* __restrict__ b_c)
{
    extern __shared__ float smf[];
    char* smem = (char*)smf;

    int tid = threadIdx.x;
    int lane = tid & 31, warp = tid >> 5;
    const float* Wd = W_dil + layer * 24576;
    const float* Wc = W_c + layer * 10240;
    const float* h_in = g_h[hsel];

    __nv_bfloat16* Ah_s = (__nv_bfloat16*)(smem + 1024);
    __nv_bfloat16* Al_s = (__nv_bfloat16*)(smem + 72704);
    __nv_bfloat16* Bh_s = (__nv_bfloat16*)(smem + 144384);
    __nv_bfloat16* Bl_s = (__nv_bfloat16*)(smem + 183296);
    float* ys = (float*)(smem + 144384);    // overlay on B region

    if (tid < 128) {
        int g = (tid & 1) ? 64 + (tid >> 1) : (tid >> 1);
        smf[tid] = b_dil[layer * 128 + g] + b_c[layer * 128 + g];
    }
    for (int i = tid; i < 128 * 272; i += 512) {
        int pg = i / 272, k = i - pg * 272;
        int g = (pg & 1) ? 64 + (pg >> 1) : (pg >> 1);
        float w = (k < 192) ? Wd[g * 192 + (k & 63) * 3 + (k >> 6)]
                            : Wc[g * 80 + (k - 192)];
        __nv_bfloat16 wh = __float2bfloat16(w);
        Ah_s[pg * 280 + k] = wh;
        Al_s[pg * 280 + k] = __float2bfloat16(w - __bfloat162float(wh));
    }
    __syncthreads();

    int m0 = (warp & 7) * 16;
    int n0 = (warp >> 3) * 64;
    int r0 = m0 + (lane >> 2);
    int q = (lane & 3) * 2;

    uint32_t sb = smem_u32(smem);
    uint32_t aBase = sb + 1024 +
        (uint32_t)(((m0 + (lane & 15)) * 280 + (lane >> 4) * 8) * 2);
    const uint32_t A_LO = 71680;
    uint32_t bBase[4];
#pragma unroll
    for (int p = 0; p < 4; p++) {
        int n = n0 + ((lane >> 4) & 1) * 8 + (lane & 7) + 16 * p;
        bBase[p] = sb + 144384 + (uint32_t)((n * 152) * 2 + (lane & 8) * 2);
    }
    const uint32_t B_LO = 38912;

    for (int tile = blockIdx.x; tile < NB * 128; tile += gridDim.x) {
        int b = tile >> 7;
        int t0 = (tile & 127) << 7;

        float d[8][4];
#pragma unroll
        for (int nt = 0; nt < 8; nt++)
#pragma unroll
            for (int e = 0; e < 4; e++) d[nt][e] = 0.f;

#pragma unroll 1
        for (int chunk = 0; chunk < 2; chunk++) {
            int ug0 = chunk ? 18 : 0;
            int ug1 = chunk ? 34 : 18;
            for (int u = ug0 * 4 + warp; u < ug1 * 4; u += 16) {
                int kg = u >> 2, nb = u & 3;
                int n = (nb << 5) + lane;
                int t = t0 + n;
                float v[8];
                if (kg < 24) {
                    int tap = kg >> 3, rb = (kg & 7) << 3;
                    int ts = t - (2 - tap) * dil;
                    const float* hp = h_in + ((b * 64 + rb) << 14) + ts;
                    if (ts >= 0) {
#pragma unroll
                        for (int j = 0; j < 8; j++) v[j] = hp[j << 14];
                    } else {
#pragma unroll
                        for (int j = 0; j < 8; j++) v[j] = 0.f;
                    }
                } else {
                    int cb = (kg - 24) << 3;
                    const float* cp = c + ((b * 80 + cb) << 14) + t;
#pragma unroll
                    for (int j = 0; j < 8; j++) v[j] = cp[j << 14];
                }
                uint32_t ph[4], pl[4];
#pragma unroll
                for (int m = 0; m < 4; m++) {
                    float a0 = v[2 * m], a1 = v[2 * m + 1];
                    __nv_bfloat16 h0 = __float2bfloat16(a0);
                    __nv_bfloat16 h1 = __float2bfloat16(a1);
                    ph[m] = pk_bf2(a0, a1);
                    pl[m] = pk_bf2(a0 - __bfloat162float(h0),
                                   a1 - __bfloat162float(h1));
                }
                int klocal = kg * 8 - (chunk ? 144 : 0);
                *(uint4*)(Bh_s + n * 152 + klocal) = make_uint4(ph[0], ph[1], ph[2], ph[3]);
                *(uint4*)(Bl_s + n * 152 + klocal) = make_uint4(pl[0], pl[1], pl[2], pl[3]);
            }
            __syncthreads();

            int nk = chunk ? 8 : 9;
            int kAbase = chunk ? 144 : 0;
#pragma unroll 1
            for (int ks = 0; ks < nk; ks++) {
                uint32_t offA = (uint32_t)((kAbase + ks * 16) * 2);
                uint32_t offB = (uint32_t)(ks * 16 * 2);
                uint32_t ah[4], al[4];
                ldsm_x4(ah, aBase + offA);
                ldsm_x4(al, aBase + A_LO + offA);
#pragma unroll
                for (int p = 0; p < 4; p++) {
                    uint32_t bh[4], bl[4];
                    ldsm_x4(bh, bBase[p] + offB);
                    ldsm_x4(bl, bBase[p] + B_LO + offB);
                    int e0 = 2 * p, e1 = 2 * p + 1;
                    mma_bf16(d[e0], ah[0], ah[1], ah[2], ah[3], bh[0], bh[1]);
                    mma_bf16(d[e0], ah[0], ah[1], ah[2], ah[3], bl[0], bl[1]);
                    mma_bf16(d[e0], al[0], al[1], al[2], al[3], bh[0], bh[1]);
                    mma_bf16(d[e1], ah[0], ah[1], ah[2], ah[3], bh[2], bh[3]);
                    mma_bf16(d[e1], ah[0], ah[1], ah[2], ah[3], bl[2], bl[3]);
                    mma_bf16(d[e1], al[0], al[1], al[2], al[3], bh[2], bh[3]);
                }
            }
            __syncthreads();
        }

#pragma unroll
        for (int nt = 0; nt < 8; nt++) {
            int col = n0 + nt * 8 + q;
            *(float2*)(ys + r0 * 132 + col)       = make_float2(d[nt][0], d[nt][1]);
            *(float2*)(ys + (r0 + 8) * 132 + col) = make_float2(d[nt][2], d[nt][3]);
        }
        __syncthreads();

        {
            int i = tid >> 3;
            int qb = tid & 7;
            float ba = smf[2 * i], bb = smf[2 * i + 1];
            const float* ya = ys + (2 * i) * 132 + qb * 16;
            const float* yb = ys + (2 * i + 1) * 132 + qb * 16;
            float* zp = &g_z[((b * 64 + i) << 14) + t0 + qb * 16];
#pragma unroll
            for (int e = 0; e < 4; e++) {
                float4 av = *(const float4*)(ya + e * 4);
                float4 bv = *(const float4*)(yb + e * 4);
                float4 zv;
                zv.x = tanhf(av.x + ba) * sigmoidf_(bv.x + bb);
                zv.y = tanhf(av.y + ba) * sigmoidf_(bv.y + bb);
                zv.z = tanhf(av.z + ba) * sigmoidf_(bv.z + bb);
                zv.w = tanhf(av.w + ba) * sigmoidf_(bv.w + bb);
                *(float4*)(zp + e * 4) = zv;
            }
        }
        __syncthreads();
    }
}

// =======================================================================
// Kernel 3 (v5 — HMMA + ldmatrix, fused hi/lo): skip+out. (unchanged R9)
// =======================================================================
#define SKIPOUT_SMEM 204288
__global__ __launch_bounds__(512) void skipout_kernel(
    int layer, int hsel,
    const float* __restrict__ W_skip, const float* __restrict__ b_skip,
    const float* __restrict__ W_out, const float* __restrict__ b_out)
{
    extern __shared__ float smf[];
    char* smem = (char*)smf;

    int tid = threadIdx.x;
    int lane = tid & 31, warp = tid >> 5;
    const float* Wsk = W_skip + layer * 256 * 64;
    const float* Wo  = W_out + layer * 64 * 64;
    const float* h_in = g_h[hsel];
    float* h_out = g_h[1 - hsel];

    float* bsk_s = smf;
    float* bo_s  = smf + 256;
    __nv_bfloat16* Ah = (__nv_bfloat16*)(smem + 1536);
    __nv_bfloat16* Al = (__nv_bfloat16*)(smem + 57856);
    __nv_bfloat16* Bh = (__nv_bfloat16*)(smem + 114176);
    __nv_bfloat16* Bl = (__nv_bfloat16*)(smem + 159232);
    const uint32_t A_LO = 56320, B_LO = 45056;

    if (tid < 256) bsk_s[tid] = b_skip[layer * 256 + tid];
    if (tid < 64)  bo_s[tid]  = b_out[layer * 64 + tid];

    for (int i = tid; i < 320 * 64; i += 512) {
        int m = i >> 6, k = i & 63;
        float w = (m < 256) ? Wsk[(m << 6) + k] : Wo[((m - 256) << 6) + k];
        __nv_bfloat16 wh = __float2bfloat16(w);
        Ah[m * 88 + k] = wh;
        Al[m * 88 + k] = __float2bfloat16(w - __bfloat162float(wh));
    }
    __syncthreads();

    int q = (lane & 3) * 2;
    int rl = lane >> 2;
    uint32_t sb = smem_u32(smem);
    uint32_t aLaneOff = (uint32_t)(((lane & 15) * 88 + (lane >> 4) * 8) * 2);
    uint32_t bLaneOff = (uint32_t)(((((lane >> 4) & 1) * 8 + (lane & 7)) * 88) * 2
                                   + (lane & 8) * 2);

    for (int tile = blockIdx.x; tile < NB * 64; tile += gridDim.x) {
        int b = tile >> 6;
        int t0 = (tile & 63) << 8;

        for (int u = warp; u < 64; u += 16) {
            int kg = u >> 3, nb = u & 7;
            int n = (nb << 5) + lane;
            int t = t0 + n;
            const float* zp = g_z + ((b * 64 + kg * 8) << 14) + t;
            float v[8];
#pragma unroll
            for (int j = 0; j < 8; j++) v[j] = zp[j << 14];
            uint32_t ph[4], pl[4];
#pragma unroll
            for (int m = 0; m < 4; m++) {
                float a0 = v[2 * m], a1 = v[2 * m + 1];
                __nv_bfloat16 h0 = __float2bfloat16(a0);
                __nv_bfloat16 h1 = __float2bfloat16(a1);
                ph[m] = pk_bf2(a0, a1);
                pl[m] = pk_bf2(a0 - __bfloat162float(h0),
                               a1 - __bfloat162float(h1));
            }
            *(uint4*)(Bh + n * 88 + kg * 8) = make_uint4(ph[0], ph[1], ph[2], ph[3]);
            *(uint4*)(Bl + n * 88 + kg * 8) = make_uint4(pl[0], pl[1], pl[2], pl[3]);
        }
        __syncthreads();

        for (int u = warp; u < 80; u += 16) {
            int mt = u >> 2, ng = u & 3;
            int m0 = mt << 4, n0g = ng << 6;
            int r0 = m0 + rl;

            uint32_t aBase = sb + 1536 + (uint32_t)(m0 * 88 * 2) + aLaneOff;
            uint32_t bBase = sb + 114176 + (uint32_t)(n0g * 88 * 2) + bLaneOff;

            float d[8][4];
#pragma unroll
            for (int nt = 0; nt < 8; nt++)
#pragma unroll
                for (int e = 0; e < 4; e++) d[nt][e] = 0.f;

#pragma unroll
            for (int ks = 0; ks < 4; ks++) {
                uint32_t off = (uint32_t)(ks * 16 * 2);
                uint32_t ah[4], al[4];
                ldsm_x4(ah, aBase + off);
                ldsm_x4(al, aBase + A_LO + off);
#pragma unroll
                for (int p = 0; p < 4; p++) {
                    uint32_t bh[4], bl[4];
                    uint32_t bp = bBase + (uint32_t)(16 * p * 88 * 2) + off;
                    ldsm_x4(bh, bp);
                    ldsm_x4(bl, bp + B_LO);
                    int e0 = 2 * p, e1 = 2 * p + 1;
                    mma_bf16(d[e0], ah[0], ah[1], ah[2], ah[3], bh[0], bh[1]);
                    mma_bf16(d[e0], ah[0], ah[1], ah[2], ah[3], bl[0], bl[1]);
                    mma_bf16(d[e0], al[0], al[1], al[2], al[3], bh[0], bh[1]);
                    mma_bf16(d[e1], ah[0], ah[1], ah[2], ah[3], bh[2], bh[3]);
                    mma_bf16(d[e1], ah[0], ah[1], ah[2], ah[3], bl[2], bl[3]);
                    mma_bf16(d[e1], al[0], al[1], al[2], al[3], bh[2], bh[3]);
                }
            }

            if (m0 < 256) {
#pragma unroll
                for (int hh = 0; hh < 2; hh++) {
                    int sc = r0 + hh * 8;
                    float bsv = bsk_s[sc];
                    float* sp = &g_skip[((b * 256 + sc) << 14) + t0 + n0g + q];
                    if (layer == 0) {
#pragma unroll
                        for (int nt = 0; nt < 8; nt++) {
                            *(float2*)(sp + nt * 8) =
                                make_float2(d[nt][hh * 2] + bsv, d[nt][hh * 2 + 1] + bsv);
                        }
                    } else {
#pragma unroll
                        for (int nt = 0; nt < 8; nt++) {
                            float2 o = *(float2*)(sp + nt * 8);
                            *(float2*)(sp + nt * 8) = make_float2(
                                (o.x + d[nt][hh * 2] + bsv) * SQRT_HALF_F,
                                (o.y + d[nt][hh * 2 + 1] + bsv) * SQRT_HALF_F);
                        }
                    }
                }
            } else {
#pragma unroll
                for (int hh = 0; hh < 2; hh++) {
                    int oc = r0 - 256 + hh * 8;
                    float bov = bo_s[oc];
                    const float* hip = h_in + ((b * 64 + oc) << 14) + t0 + n0g + q;
                    float* hop = h_out + ((b * 64 + oc) << 14) + t0 + n0g + q;
#pragma unroll
                    for (int nt = 0; nt < 8; nt++) {
                        float2 hv = *(const float2*)(hip + nt * 8);
                        *(float2*)(hop + nt * 8) = make_float2(
                            (d[nt][hh * 2] + bov + hv.x) * SQRT_HALF_F,
                            (d[nt][hh * 2 + 1] + bov + hv.y) * SQRT_HALF_F);
                    }
                }
            }
        }
        __syncthreads();
    }
}

// =======================================================================
// Kernel 4 (v4 — HMMA + ldmatrix): dense 256x256, prepped weights. (R10)
// =======================================================================
#define DENSE_SMEM 209920
__global__ __launch_bounds__(512) void dense_hmma_kernel(
    int stage, float* __restrict__ final_out, const float* __restrict__ bias)
{
    extern __shared__ float smf[];
    char* smem = (char*)smf;

    int tid = threadIdx.x;
    int lane = tid & 31, warp = tid >> 5;

    const float* in = (stage == 0) ? g_skip : g_tmp;
    float* out = (stage == 0) ? g_tmp : final_out;

    float* bb = smf;
    __nv_bfloat16* AhS = (__nv_bfloat16*)(smem + 1024);
    __nv_bfloat16* AlS = (__nv_bfloat16*)(smem + 70656);
    __nv_bfloat16* BhS = (__nv_bfloat16*)(smem + 140288);
    __nv_bfloat16* BlS = (__nv_bfloat16*)(smem + 175104);
    const uint32_t A_LO = 69632, B_LO = 34816;

    if (tid < 256) bb[tid] = bias[tid];

    int mt = warp;
    int q = (lane & 3) * 2;
    int rl = lane >> 2;

    uint32_t sb = smem_u32(smem);
    uint32_t aBase = sb + 1024 +
        (uint32_t)(((mt * 16 + (lane & 15)) * 136 + (lane >> 4) * 8) * 2);
    uint32_t bBase[8];
#pragma unroll
    for (int p = 0; p < 8; p++) {
        int n = ((lane >> 4) & 1) * 8 + (lane & 7) + 16 * p;
        bBase[p] = sb + 140288 + (uint32_t)((n * 136) * 2 + (lane & 8) * 2);
    }

    for (int tile = blockIdx.x; tile < NB * 128; tile += gridDim.x) {
        int b = tile >> 7;
        int t0 = (tile & 127) << 7;

        float d[16][4];
#pragma unroll
        for (int nt = 0; nt < 16; nt++)
#pragma unroll
            for (int e = 0; e < 4; e++) d[nt][e] = 0.f;

#pragma unroll 1
        for (int chunk = 0; chunk < 2; chunk++) {
            __syncthreads();
            {
                const uint4* gh = (const uint4*)g_dwh[stage][chunk];
                const uint4* gl = (const uint4*)g_dwl[stage][chunk];
                uint4* sh = (uint4*)AhS;
                uint4* sl = (uint4*)AlS;
                for (int i = tid; i < 4352; i += 512) {
                    sh[i] = gh[i];
                    sl[i] = gl[i];
                }
            }
            for (int u = warp; u < 64; u += 16) {
                int kg = u >> 2, nb = u & 3;
                int n = (nb << 5) + lane;
                int t = t0 + n;
                const float* ip = in + ((b * 256 + chunk * 128 + kg * 8) << 14) + t;
                float v[8];
#pragma unroll
                for (int j = 0; j < 8; j++) {
                    float xv = ip[j << 14];
                    v[j] = (stage == 0) ? fmaxf(xv, 0.f) : xv;
                }
                uint32_t ph[4], pl[4];
#pragma unroll
                for (int m = 0; m < 4; m++) {
                    float a0 = v[2 * m], a1 = v[2 * m + 1];
                    __nv_bfloat16 h0 = __float2bfloat16(a0);
                    __nv_bfloat16 h1 = __float2bfloat16(a1);
                    ph[m] = pk_bf2(a0, a1);
                    pl[m] = pk_bf2(a0 - __bfloat162float(h0),
                                   a1 - __bfloat162float(h1));
                }
                *(uint4*)(BhS + n * 136 + kg * 8) = make_uint4(ph[0], ph[1], ph[2], ph[3]);
                *(uint4*)(BlS + n * 136 + kg * 8) = make_uint4(pl[0], pl[1], pl[2], pl[3]);
            }
            __syncthreads();

#pragma unroll 1
            for (int ks = 0; ks < 8; ks++) {
                uint32_t off = (uint32_t)(ks * 16 * 2);
                uint32_t ah[4], al[4];
                ldsm_x4(ah, aBase + off);
                ldsm_x4(al, aBase + A_LO + off);
#pragma unroll
                for (int p = 0; p < 8; p++) {
                    uint32_t bh[4], bl[4];
                    ldsm_x4(bh, bBase[p] + off);
                    ldsm_x4(bl, bBase[p] + B_LO + off);
                    int e0 = 2 * p, e1 = 2 * p + 1;
                    mma_bf16(d[e0], ah[0], ah[1], ah[2], ah[3], bh[0], bh[1]);
                    mma_bf16(d[e0], ah[0], ah[1], ah[2], ah[3], bl[0], bl[1]);
                    mma_bf16(d[e0], al[0], al[1], al[2], al[3], bh[0], bh[1]);
                    mma_bf16(d[e1], ah[0], ah[1], ah[2], ah[3], bh[2], bh[3]);
                    mma_bf16(d[e1], ah[0], ah[1], ah[2], ah[3], bl[2], bl[3]);
                    mma_bf16(d[e1], al[0], al[1], al[2], al[3], bh[2], bh[3]);
                }
            }
        }

#pragma unroll
        for (int hh = 0; hh < 2; hh++) {
            int oc = mt * 16 + rl + hh * 8;
            float bv = bb[oc];
            float* op = out + ((b * 256 + oc) << 14) + t0;
#pragma unroll
            for (int nt = 0; nt < 16; nt++) {
                int col = (nt >> 1) * 16 + (nt & 1) * 8 + q;
                float2 v = make_float2(d[nt][hh * 2] + bv, d[nt][hh * 2 + 1] + bv);
                if (stage == 0) {
                    v.x = fmaxf(v.x, 0.f);
                    v.y = fmaxf(v.y, 0.f);
                }
                *(float2*)(op + col) = v;
            }
        }
    }
}

// =======================================================================
extern "C" void kernel_launch(void* const* d_in, const int* in_sizes, int n_in,
                              void* d_out, int out_size)
{
    const float* x       = (const float*)d_in[0];
    const float* c       = (const float*)d_in[1];
    const float* W_first = (const float*)d_in[2];
    const float* b_first = (const float*)d_in[3];
    const float* W_dil   = (const float*)d_in[4];
    const float* b_dil   = (const float*)d_in[5];
    const float* W_c     = (const float*)d_in[6];
    const float* b_c     = (const float*)d_in[7];
    const float* W_skip  = (const float*)d_in[8];
    const float* b_skip  = (const float*)d_in[9];
    const float* W_out   = (const float*)d_in[10];
    const float* b_out   = (const float*)d_in[11];
    const float* W_last1 = (const float*)d_in[12];
    const float* b_last1 = (const float*)d_in[13];
    const float* W_last2 = (const float*)d_in[14];
    const float* b_last2 = (const float*)d_in[15];
    float* out = (float*)d_out;

    cudaFuncSetAttribute(first_hmma_kernel, cudaFuncAttributeMaxDynamicSharedMemorySize, FIRST_SMEM);
    cudaFuncSetAttribute(gate_kernel,   cudaFuncAttributeMaxDynamicSharedMemorySize, GATE_SMEM);
    cudaFuncSetAttribute(skipout_kernel,cudaFuncAttributeMaxDynamicSharedMemorySize, SKIPOUT_SMEM);
    cudaFuncSetAttribute(dense_hmma_kernel,cudaFuncAttributeMaxDynamicSharedMemorySize, DENSE_SMEM);

    int dev = 0;
    cudaGetDevice(&dev);
    int sm_count = 148;
    cudaDeviceGetAttribute(&sm_count, cudaDevAttrMultiProcessorCount, dev);
    int grid1 = sm_count;

    prep_dense_kernel<<<256, 512>>>(W_last1, W_last2);
    first_hmma_kernel<<<grid1, 512, FIRST_SMEM>>>(x, W_first, b_first);

    for (int l = 0; l < 20; l++) {
        int dil = 1 << (l % 10);
        int hsel = l & 1;
        gate_kernel<<<grid1, 512, GATE_SMEM>>>(l, dil, hsel, c,
                                               W_dil, b_dil, W_c, b_c);
        skipout_kernel<<<grid1, 512, SKIPOUT_SMEM>>>(l, hsel,
                                                     W_skip, b_skip, W_out, b_out);
    }

    dense_hmma_kernel<<<grid1, 512, DENSE_SMEM>>>(0, out, b_last1);
    dense_hmma_kernel<<<grid1, 512, DENSE_SMEM>>>(1, out, b_last2);
}